// round 14
// baseline (speedup 1.0000x reference)
#include <cuda_runtime.h>
#include <math.h>

#define NB 16
#define SDIM 512

typedef unsigned long long ull;

__device__ __forceinline__ ull pack2(float a, float b) {
    ull r;
    asm("mov.b64 %0, {%1, %2};" : "=l"(r) : "f"(a), "f"(b));
    return r;
}
__device__ __forceinline__ void unpack2(ull v, float& a, float& b) {
    asm("mov.b64 {%0, %1}, %2;" : "=f"(a), "=f"(b) : "l"(v));
}
__device__ __forceinline__ void ffma2(ull& d, ull a, ull b) {
    asm("fma.rn.f32x2 %0, %1, %2, %0;" : "+l"(d) : "l"(a), "l"(b));
}

// ---------------- persistent scratch (no allocs allowed) ----------------
static __device__ float g_bufA[16777216];   // max: (16,64,128,128)
static __device__ float g_bufB[17040384];   // max: (16,64,129,129)
static __device__ float g_part[16777216];   // split-K partials (up to 8 halves)

static __device__ float g_style0[NB * 256];
static __device__ float g_style1[NB * 128];
static __device__ float g_style2[NB * 128];
static __device__ float g_style3[NB * 64];
static __device__ float g_style4[NB * 64];
static __device__ float g_stylef[NB * 32];

static __device__ float g_demod0[NB * 128];
static __device__ float g_demod1[NB * 128];
static __device__ float g_demod2[NB * 64];
static __device__ float g_demod3[NB * 64];
static __device__ float g_demod4[NB * 32];

__device__ __forceinline__ float* style_ptr(int id) {
    switch (id) {
        case 0: return g_style0;
        case 1: return g_style1;
        case 2: return g_style2;
        case 3: return g_style3;
        case 4: return g_style4;
        default: return g_stylef;
    }
}
__device__ __forceinline__ float* demod_ptr(int id) {
    switch (id) {
        case 0: return g_demod0;
        case 1: return g_demod1;
        case 2: return g_demod2;
        case 3: return g_demod3;
        default: return g_demod4;
    }
}

struct P6 { const float* a[6]; };
struct P5 { const float* a[5]; };

// ---------------- fused style kernel: all 6 layers ----------------
__global__ void style_all_kernel(const float* __restrict__ z, P6 mw, P6 mb) {
    int gw = blockIdx.x * 8 + (threadIdx.x >> 5);
    int lane = threadIdx.x & 31;
    if (gw >= NB * 672) return;
    int b = gw / 672;
    int c = gw - b * 672;
    int L, ci, Ci;
    if (c < 256)      { L = 0; ci = c;       Ci = 256; }
    else if (c < 384) { L = 1; ci = c - 256; Ci = 128; }
    else if (c < 512) { L = 2; ci = c - 384; Ci = 128; }
    else if (c < 576) { L = 3; ci = c - 512; Ci = 64; }
    else if (c < 640) { L = 4; ci = c - 576; Ci = 64; }
    else              { L = 5; ci = c - 640; Ci = 32; }
    const float* zr = z + b * SDIM;
    const float* mr = mw.a[L] + (size_t)ci * SDIM;
    float s = 0.f;
#pragma unroll 4
    for (int k = lane; k < SDIM; k += 32) s += zr[k] * mr[k];
#pragma unroll
    for (int o = 16; o; o >>= 1) s += __shfl_xor_sync(0xffffffffu, s, o);
    if (lane == 0)
        style_ptr(L)[b * Ci + ci] = s * 0.04419417382415922f + mb.a[L][ci];
}

// ---------------- fused demod kernel, wsq inline ----------------
__global__ void demod_all_kernel(P5 w) {
    int gw = blockIdx.x * 8 + (threadIdx.x >> 5);
    int lane = threadIdx.x & 31;
    if (gw >= NB * 416) return;
    int b = gw / 416;
    int c = gw - b * 416;
    int L, co, Co, Ci;
    if (c < 128)      { L = 0; co = c;       Co = 128; Ci = 256; }
    else if (c < 256) { L = 1; co = c - 128; Co = 128; Ci = 128; }
    else if (c < 320) { L = 2; co = c - 256; Co = 64;  Ci = 128; }
    else if (c < 384) { L = 3; co = c - 320; Co = 64;  Ci = 64; }
    else              { L = 4; co = c - 384; Co = 32;  Ci = 64; }
    const float* st = style_ptr(L) + b * Ci;
    const float* wb = w.a[L] + (size_t)co * Ci * 9;
    float s = 0.f;
    for (int ci = lane; ci < Ci; ci += 32) {
        const float* p = wb + ci * 9;
        float wq = 0.f;
#pragma unroll
        for (int t = 0; t < 9; t++) wq += p[t] * p[t];
        float sv = st[ci];
        s += sv * sv * wq;
    }
#pragma unroll
    for (int o = 16; o; o >>= 1) s += __shfl_xor_sync(0xffffffffu, s, o);
    if (lane == 0)
        demod_ptr(L)[b * Co + co] = rsqrtf(s * (1.0f / (float)(Ci * 9)) + 1e-8f);
}

// ---------------- compose: bufA = (fg + (1-mask)*bg) * style0 ----------------
__global__ void compose_kernel(const float* __restrict__ fg,
                               const float* __restrict__ mask,
                               const float* __restrict__ bg) {
    int idx = blockIdx.x * blockDim.x + threadIdx.x;
    int p = idx & 1023;
    int c = (idx >> 10) & 255;
    int b = idx >> 18;
    float m = 1.0f - mask[b * 1024 + p];
    float v = fg[idx] + m * bg[idx];
    g_bufA[idx] = v * g_style0[b * 256 + c];
}

// ---------------- 3x3 conv, pad 1, f32x2; shift/mask staging; split-K -------
template <int CIN_TOT, int CIN_DO, int COUT, int H, int W, bool SRC_A, int CO_T,
          int NSPLIT>
__global__ __launch_bounds__(256) void conv3x3_kernel(const float* __restrict__ wraw,
                                                      const float* __restrict__ bias,
                                                      int demod_id, int style_id) {
    constexpr int CI_T = 8, TH = 8, TW = 32;
    constexpr int CO_PW = CO_T / 8;
    constexpr int JP = CO_PW / 2;
    constexpr int IN_LD = 36;
    constexpr int W_LD = CO_T + 2;
    constexpr int TILES_X = W / TW;
    __shared__ __align__(16) float s_in[TH + 2][CI_T + 1][IN_LD];
    __shared__ __align__(16) float s_w[CI_T][9][W_LD];

    const float* in = SRC_A ? g_bufA : g_bufB;
    float* out = SRC_A ? g_bufB : g_bufA;
    const float* demod = demod_ptr(demod_id);
    const float* styn = style_ptr(style_id);

    int tid = threadIdx.x;
    int tile = blockIdx.x;
    int tx0 = (tile % TILES_X) * TW;
    int ty0 = (tile / TILES_X) * TH;
    int co_base = blockIdx.y * CO_T;

    int b = blockIdx.z / NSPLIT;
    int half = blockIdx.z % NSPLIT;
    int cin_off = half * CIN_DO;

    int warp = tid >> 5;
    int lane = tid & 31;
    int r = lane >> 2;
    int c0 = (lane & 3) << 3;

    ull acc[JP][8];
#pragma unroll
    for (int jp = 0; jp < JP; jp++)
#pragma unroll
        for (int p = 0; p < 8; p++) acc[jp][p] = 0ull;

    const float wscale = rsqrtf((float)(CIN_TOT * 9));
    const float* in_b = in + (size_t)b * CIN_TOT * H * W;

    int colA = tid & 31;
    int gxA = tx0 + colA - 1;
    bool gxA_ok = (gxA >= 0 && gxA < W);
    int ixB = 32 + (tid & 1);
    int rowB = tid >> 1;
    int iyB = rowB >> 3, ciB = rowB & 7;
    int gxB = tx0 + ixB - 1;
    int gyB = ty0 + iyB - 1;
    bool B_ok = (tid < 160) && gxB >= 0 && gxB < W && gyB >= 0 && gyB < H;

    for (int cb = 0; cb < CIN_DO; cb += CI_T) {
        __syncthreads();
        const float* in_c = in_b + (size_t)(cin_off + cb) * H * W;
#pragma unroll
        for (int k = 0; k < 10; k++) {
            int rowq = (tid + k * 256) >> 5;
            int iy = rowq >> 3;
            int ci = rowq & 7;
            int gy = ty0 + iy - 1;
            float v = 0.f;
            if (gy >= 0 && gy < H && gxA_ok)
                v = in_c[ci * H * W + gy * W + gxA];
            s_in[iy][ci][colA] = v;
        }
        {
            float v = 0.f;
            if (B_ok) v = in_c[ciB * H * W + gyB * W + gxB];
            if (tid < 160) s_in[iyB][ciB][ixB] = v;
        }
#pragma unroll
        for (int k = 0; k < 9; k++) {
            int idx = tid + k * 256;
            int co = idx / (CI_T * 9);
            int rem = idx % (CI_T * 9);
            int ci = rem / 9, tap = rem % 9;
            s_w[ci][tap][co] =
                wraw[((size_t)(co_base + co) * CIN_TOT + cin_off + cb + ci) * 9 +
                     tap] * wscale;
        }
        __syncthreads();
#pragma unroll
        for (int ci = 0; ci < CI_T; ci++) {
#pragma unroll
            for (int ky = 0; ky < 3; ky++) {
                const float4* row4 =
                    reinterpret_cast<const float4*>(&s_in[r + ky][ci][c0]);
                float4 q0 = row4[0];
                float4 q1 = row4[1];
                float4 q2 = row4[2];
                ull xd[10];
                xd[0] = pack2(q0.x, q0.x); xd[1] = pack2(q0.y, q0.y);
                xd[2] = pack2(q0.z, q0.z); xd[3] = pack2(q0.w, q0.w);
                xd[4] = pack2(q1.x, q1.x); xd[5] = pack2(q1.y, q1.y);
                xd[6] = pack2(q1.z, q1.z); xd[7] = pack2(q1.w, q1.w);
                xd[8] = pack2(q2.x, q2.x); xd[9] = pack2(q2.y, q2.y);
#pragma unroll
                for (int kx = 0; kx < 3; kx++) {
#pragma unroll
                    for (int jp = 0; jp < JP; jp++) {
                        ull w2 = *reinterpret_cast<const ull*>(
                            &s_w[ci][ky * 3 + kx][warp * CO_PW + jp * 2]);
#pragma unroll
                        for (int p = 0; p < 8; p++) ffma2(acc[jp][p], w2, xd[kx + p]);
                    }
                }
            }
        }
    }
    int oy = ty0 + r;
#pragma unroll
    for (int jp = 0; jp < JP; jp++) {
        float vlo[8], vhi[8];
#pragma unroll
        for (int p = 0; p < 8; p++) unpack2(acc[jp][p], vlo[p], vhi[p]);
#pragma unroll
        for (int h = 0; h < 2; h++) {
            int co = co_base + warp * CO_PW + jp * 2 + h;
            const float* src = h ? vhi : vlo;
            if (NSPLIT > 1) {
                float* pp = g_part +
                            (((size_t)half * NB + b) * COUT + co) * H * W +
                            oy * W + tx0 + c0;
                float4 o0, o1;
                o0.x = src[0]; o0.y = src[1]; o0.z = src[2]; o0.w = src[3];
                o1.x = src[4]; o1.y = src[5]; o1.z = src[6]; o1.w = src[7];
                reinterpret_cast<float4*>(pp)[0] = o0;
                reinterpret_cast<float4*>(pp)[1] = o1;
            } else {
                float dm = demod[b * COUT + co];
                float bi = bias[co];
                float sn = styn[b * COUT + co];
                float* op = out + (size_t)b * COUT * H * W +
                            (size_t)co * H * W + oy * W + tx0 + c0;
                float4 o0, o1;
                float vv[8];
#pragma unroll
                for (int p = 0; p < 8; p++) {
                    float v = src[p] * dm + bi;
                    vv[p] = (v > 0.f ? v : 0.2f * v) * 1.41421356237309515f * sn;
                }
                o0.x = vv[0]; o0.y = vv[1]; o0.z = vv[2]; o0.w = vv[3];
                o1.x = vv[4]; o1.y = vv[5]; o1.z = vv[6]; o1.w = vv[7];
                reinterpret_cast<float4*>(op)[0] = o0;
                reinterpret_cast<float4*>(op)[1] = o1;
            }
        }
    }
}

// ---------------- split-K combine ----------------
template <int CO, int HW, int NHALF, bool DST_B>
__global__ void combine_kernel(const float* __restrict__ bias,
                               int demod_id, int style_id) {
    int idx = blockIdx.x * blockDim.x + threadIdx.x;
    constexpr int COHW = CO * HW;
    int b = idx / COHW;
    int co = (idx / HW) & (CO - 1);
    float p = 0.f;
#pragma unroll
    for (int h = 0; h < NHALF; h++) p += g_part[idx + (size_t)h * NB * COHW];
    float v = p * demod_ptr(demod_id)[b * CO + co] + bias[co];
    v = (v > 0.f ? v : 0.2f * v) * 1.41421356237309515f *
        style_ptr(style_id)[b * CO + co];
    (DST_B ? g_bufB : g_bufA)[idx] = v;
}

// ---------------- transposed conv: dense interior (R12 winner) --------------
template <int CIN, int COUT, int HIN, bool SRC_A>
__global__ __launch_bounds__(256) void tconv_kernel(const float* __restrict__ wraw,
                                                    int demod_id) {
    constexpr int HOUT = 2 * HIN + 1;
    constexpr int CO_T = 32, CI_T = 8, TH = 8, TW = 32;
    constexpr int IR = 6, ICW = 18, IC_LD = 19;
    constexpr int W_LD = 34;
    constexpr int TILES_X = (2 * HIN) / TW;
    __shared__ __align__(16) float s_in[CI_T][IR][IC_LD];
    __shared__ __align__(16) float s_w[CI_T][9][W_LD];

    const float* in = SRC_A ? g_bufA : g_bufB;
    float* out = SRC_A ? g_bufB : g_bufA;
    const float* demod = demod_ptr(demod_id);

    int tid = threadIdx.x;
    int tile = blockIdx.x;
    int tx0 = (tile % TILES_X) * TW;
    int ty0 = (tile / TILES_X) * TH;
    int co_base = blockIdx.y * CO_T;
    int b = blockIdx.z;

    int co_grp = tid >> 6;
    int lane = tid & 31;
    int wrp = tid >> 5;
    int r = 2 * ((lane >> 3) & 3) + (wrp & 1);
    int c0 = (lane & 7) << 2;
    int h = c0 >> 1;

    int iy_base = (ty0 >> 1) - 1;
    int jx_base = (tx0 >> 1) - 1;

    ull acc[4][4];
#pragma unroll
    for (int jp = 0; jp < 4; jp++)
#pragma unroll
        for (int p = 0; p < 4; p++) acc[jp][p] = 0ull;

    const float wscale = rsqrtf((float)(CIN * 9));
    const float* in_b = in + (size_t)b * CIN * HIN * HIN;

    for (int cb = 0; cb < CIN; cb += CI_T) {
        __syncthreads();
        for (int idx = tid; idx < CI_T * IR * ICW; idx += 256) {
            int ci = idx / (IR * ICW);
            int rem = idx % (IR * ICW);
            int iy = rem / ICW, ix = rem % ICW;
            int gy = iy_base + iy, gx = jx_base + ix;
            float v = 0.f;
            if (gy >= 0 && gy < HIN && gx >= 0 && gx < HIN)
                v = in_b[(size_t)(cb + ci) * HIN * HIN + gy * HIN + gx];
            s_in[ci][iy][ix] = v;
        }
        for (int idx = tid; idx < CO_T * CI_T * 9; idx += 256) {
            int co = idx / (CI_T * 9);
            int rem = idx % (CI_T * 9);
            int ci = rem / 9, tap = rem % 9;
            s_w[ci][tap][co] =
                wraw[((size_t)(co_base + co) * CIN + cb + ci) * 9 + tap] * wscale;
        }
        __syncthreads();
#pragma unroll
        for (int ci = 0; ci < CI_T; ci++) {
            int ky0 = r & 1;
            for (int ky = ky0; ky < 3; ky += 2) {
                int ir = ((r + ky - 2) >> 1) + 1;
                float x0v = s_in[ci][ir][h];
                float x1v = s_in[ci][ir][h + 1];
                float x2v = s_in[ci][ir][h + 2];
                ull xd0 = pack2(x0v, x0v);
                ull xd1 = pack2(x1v, x1v);
                ull xd2 = pack2(x2v, x2v);
                int wr = (2 - ky) * 3;
#pragma unroll
                for (int jp = 0; jp < 4; jp++) {
                    int co = co_grp * 8 + jp * 2;
                    ull w0 = *reinterpret_cast<const ull*>(&s_w[ci][wr + 0][co]);
                    ull w1 = *reinterpret_cast<const ull*>(&s_w[ci][wr + 1][co]);
                    ull w2 = *reinterpret_cast<const ull*>(&s_w[ci][wr + 2][co]);
                    ffma2(acc[jp][0], w2, xd0);
                    ffma2(acc[jp][0], w0, xd1);
                    ffma2(acc[jp][1], w1, xd1);
                    ffma2(acc[jp][2], w2, xd1);
                    ffma2(acc[jp][2], w0, xd2);
                    ffma2(acc[jp][3], w1, xd2);
                }
            }
        }
    }
    int oy = ty0 + r;   // < 2*HIN by construction
    float* out_b = out + (size_t)b * COUT * HOUT * HOUT;
#pragma unroll
    for (int jp = 0; jp < 4; jp++) {
#pragma unroll
        for (int hh = 0; hh < 2; hh++) {
            int co = co_base + co_grp * 8 + jp * 2 + hh;
            float dm = demod[b * COUT + co];
#pragma unroll
            for (int p = 0; p < 4; p++) {
                float lo, hi;
                unpack2(acc[jp][p], lo, hi);
                out_b[(size_t)co * HOUT * HOUT + oy * HOUT + tx0 + c0 + p] =
                    (hh ? hi : lo) * dm;
            }
        }
    }
}

// ---------------- tconv edge strips (unchanged R12 winner) ------------------
template <int CIN, int COUT, int HIN, bool SRC_A>
__global__ __launch_bounds__(256) void tconv_edge_kernel(
    const float* __restrict__ wraw, int demod_id) {
    constexpr int HOUT = 2 * HIN + 1;
    __shared__ float s_line[CIN][HIN];
    __shared__ float s_w3[CIN][3][33];

    const float* in = SRC_A ? g_bufA : g_bufB;
    float* out = SRC_A ? g_bufB : g_bufA;

    int s = blockIdx.y;
    int co_base = blockIdx.x * 32;
    int b = blockIdx.z;
    int tid = threadIdx.x;
    const float* in_b = in + (size_t)b * CIN * HIN * HIN;

    for (int e = tid; e < CIN * HIN; e += 256) {
        int ci = e / HIN, t = e % HIN;
        s_line[ci][t] = (s == 0)
            ? in_b[(size_t)ci * HIN * HIN + t * HIN + (HIN - 1)]
            : in_b[(size_t)ci * HIN * HIN + (HIN - 1) * HIN + t];
    }
    const float wscale = rsqrtf((float)(CIN * 9));
    for (int e = tid; e < 32 * CIN * 3; e += 256) {
        int co = e / (CIN * 3);
        int rem = e % (CIN * 3);
        int ci = rem / 3, k = rem % 3;
        int widx = (s == 0) ? ((2 - k) * 3 + 2) : (2 * 3 + (2 - k));
        s_w3[ci][k][co] =
            wraw[((size_t)(co_base + co) * CIN + ci) * 9 + widx] * wscale;
    }
    __syncthreads();

    int co = tid & 31;
    float dm = demod_ptr(demod_id)[b * COUT + co_base + co];
    float* out_b = out + ((size_t)b * COUT + co_base + co) * HOUT * HOUT;
    int nmax = HOUT - s;
    for (int n = tid >> 5; n < nmax; n += 8) {
        float acc = 0.f;
        if (n & 1) {
            int iy = (n - 1) >> 1;
#pragma unroll 4
            for (int ci = 0; ci < CIN; ci++)
                acc += s_line[ci][iy] * s_w3[ci][1][co];
        } else {
            int hh = n >> 1;
            if (hh >= 1) {
#pragma unroll 4
                for (int ci = 0; ci < CIN; ci++)
                    acc += s_line[ci][hh - 1] * s_w3[ci][0][co];
            }
            if (hh < HIN) {
#pragma unroll 4
                for (int ci = 0; ci < CIN; ci++)
                    acc += s_line[ci][hh] * s_w3[ci][2][co];
            }
        }
        acc *= dm;
        if (s == 0) out_b[n * HOUT + (HOUT - 1)] = acc;
        else out_b[(HOUT - 1) * HOUT + n] = acc;
    }
}

// ---------------- 4x4 blur + bias + leaky*sqrt2*style_next ----------------
template <int C, int HIN, bool SRC_A>
__global__ __launch_bounds__(256) void blur_kernel(const float* __restrict__ bias,
                                                   int style_id) {
    constexpr int HOUT = HIN - 1;
    constexpr int TH = 16, TW = 32;
    constexpr int TILES_X = HOUT / TW;
    __shared__ float s[TH + 3][TW + 4];

    const float* in = SRC_A ? g_bufA : g_bufB;
    float* out = SRC_A ? g_bufB : g_bufA;

    int tile = blockIdx.x;
    int x0 = (tile % TILES_X) * TW;
    int y0 = (tile / TILES_X) * TH;
    int c = blockIdx.y, b = blockIdx.z;
    const float* ip = in + ((size_t)b * C + c) * HIN * HIN;

    for (int idx = threadIdx.x; idx < (TH + 3) * (TW + 3); idx += 256) {
        int iy = idx / (TW + 3), ix = idx % (TW + 3);
        int gy = y0 + iy - 1, gx = x0 + ix - 1;
        float v = 0.f;
        if (gy >= 0 && gy < HIN && gx >= 0 && gx < HIN) v = ip[gy * HIN + gx];
        s[iy][ix] = v;
    }
    __syncthreads();

    const float c4[4] = {0.25f, 0.75f, 0.75f, 0.25f};
    float bi = bias[c];
    float sn = style_ptr(style_id)[b * C + c];
    float* op = out + ((size_t)b * C + c) * HOUT * HOUT;
#pragma unroll
    for (int q = 0; q < 2; q++) {
        int px = threadIdx.x + q * 256;
        int ly = px >> 5, lx = px & 31;
        float a = 0.f;
#pragma unroll
        for (int ky = 0; ky < 4; ky++) {
            float rs = 0.f;
#pragma unroll
            for (int kx = 0; kx < 4; kx++) rs += c4[kx] * s[ly + ky][lx + kx];
            a += c4[ky] * rs;
        }
        a += bi;
        a = (a > 0.f ? a : 0.2f * a) * 1.41421356237309515f * sn;
        op[(y0 + ly) * HOUT + x0 + lx] = a;
    }
}

// ---------------- final 1x1 (32 -> 3 of 4 ch), + out_bias ----------------
__global__ void final_kernel(const float* __restrict__ finw,
                             const float* __restrict__ outb,
                             float* __restrict__ out) {
    int idx = blockIdx.x * blockDim.x + threadIdx.x;
    int b = idx >> 14;
    int p = idx & 16383;
    const float* ib = g_bufB + (size_t)b * 32 * 16384 + p;
    float a0 = 0.f, a1 = 0.f, a2 = 0.f;
#pragma unroll
    for (int ci = 0; ci < 32; ci++) {
        float v = ib[(size_t)ci * 16384];
        a0 = fmaf(finw[ci], v, a0);
        a1 = fmaf(finw[32 + ci], v, a1);
        a2 = fmaf(finw[64 + ci], v, a2);
    }
    const float sc = rsqrtf(32.0f);
    out[(size_t)b * 3 * 16384 + p] = a0 * sc + outb[0];
    out[(size_t)b * 3 * 16384 + 16384 + p] = a1 * sc + outb[1];
    out[(size_t)b * 3 * 16384 + 2 * 16384 + p] = a2 * sc + outb[2];
}

// ------------------------------------------------------------------------
extern "C" void kernel_launch(void* const* d_in, const int* in_sizes, int n_in,
                              void* d_out, int out_size) {
    (void)in_sizes; (void)n_in; (void)out_size;
    const float* fg = (const float*)d_in[0];
    const float* mask = (const float*)d_in[1];
    const float* bg = (const float*)d_in[2];
    const float* z = (const float*)d_in[3];
    const float* l_w[5]  = {(const float*)d_in[4],  (const float*)d_in[8],
                            (const float*)d_in[12], (const float*)d_in[16],
                            (const float*)d_in[20]};
    const float* l_mw[5] = {(const float*)d_in[5],  (const float*)d_in[9],
                            (const float*)d_in[13], (const float*)d_in[17],
                            (const float*)d_in[21]};
    const float* l_mb[5] = {(const float*)d_in[6],  (const float*)d_in[10],
                            (const float*)d_in[14], (const float*)d_in[18],
                            (const float*)d_in[22]};
    const float* l_b[5]  = {(const float*)d_in[7],  (const float*)d_in[11],
                            (const float*)d_in[15], (const float*)d_in[19],
                            (const float*)d_in[23]};
    const float* finw = (const float*)d_in[24];
    const float* fin_mw = (const float*)d_in[25];
    const float* fin_mb = (const float*)d_in[26];
    const float* outb = (const float*)d_in[27];

    // fused setup: 2 kernels
    P6 mw6, mb6;
    for (int l = 0; l < 5; l++) { mw6.a[l] = l_mw[l]; mb6.a[l] = l_mb[l]; }
    mw6.a[5] = fin_mw; mb6.a[5] = fin_mb;
    style_all_kernel<<<1344, 256>>>(z, mw6, mb6);
    P5 w5;
    for (int l = 0; l < 5; l++) w5.a[l] = l_w[l];
    demod_all_kernel<<<832, 256>>>(w5);

    // compose + modulate for layer 0 -> bufA
    compose_kernel<<<(NB * 256 * 1024) / 256, 256>>>(fg, mask, bg);

    // l0: 256->128 @32x32, split-K=8 -> 2048 CTAs (wave packing)
    conv3x3_kernel<256, 32, 128, 32, 32, true, 32, 8>
        <<<dim3(4, 4, 128), 256>>>(l_w[0], l_b[0], 0, 1);
    combine_kernel<128, 1024, 8, true><<<8192, 256>>>(l_b[0], 0, 1);
    // l1: tconv 128->128, 32 -> 65 (B -> A): dense 64x64 interior + edges
    tconv_kernel<128, 128, 32, false><<<dim3(16, 4, NB), 256>>>(l_w[1], 1);
    tconv_edge_kernel<128, 128, 32, false><<<dim3(4, 2, NB), 256>>>(l_w[1], 1);
    // blur 65 -> 64 + act + style2   (A -> B)
    blur_kernel<128, 65, true><<<dim3(8, 128, NB), 256>>>(l_b[1], 2);
    // l2: 128->64 @64x64, split-K=4 -> 2048 CTAs
    conv3x3_kernel<128, 32, 64, 64, 64, false, 32, 4>
        <<<dim3(16, 2, 64), 256>>>(l_w[2], l_b[2], 2, 3);
    combine_kernel<64, 4096, 4, false><<<16384, 256>>>(l_b[2], 2, 3);
    // l3: tconv 64->64, 64 -> 129 (A -> B): dense 128x128 interior + edges
    tconv_kernel<64, 64, 64, true><<<dim3(64, 2, NB), 256>>>(l_w[3], 3);
    tconv_edge_kernel<64, 64, 64, true><<<dim3(2, 2, NB), 256>>>(l_w[3], 3);
    // blur 129 -> 128 + act + style4   (B -> A)
    blur_kernel<64, 129, false><<<dim3(32, 64, NB), 256>>>(l_b[3], 4);
    // l4: 64->32 @128x128   (A -> B)
    conv3x3_kernel<64, 64, 32, 128, 128, true, 32, 1>
        <<<dim3(64, 1, 16), 256>>>(l_w[4], l_b[4], 4, 5);
    // final 1x1 32->3 + out_bias   (B -> d_out)
    final_kernel<<<(NB * 16384) / 256, 256>>>(finw, outb, (float*)d_out);
}

// round 15
// speedup vs baseline: 1.0076x; 1.0076x over previous
#include <cuda_runtime.h>
#include <math.h>

#define NB 16
#define SDIM 512

typedef unsigned long long ull;

__device__ __forceinline__ ull pack2(float a, float b) {
    ull r;
    asm("mov.b64 %0, {%1, %2};" : "=l"(r) : "f"(a), "f"(b));
    return r;
}
__device__ __forceinline__ void unpack2(ull v, float& a, float& b) {
    asm("mov.b64 {%0, %1}, %2;" : "=f"(a), "=f"(b) : "l"(v));
}
__device__ __forceinline__ void ffma2(ull& d, ull a, ull b) {
    asm("fma.rn.f32x2 %0, %1, %2, %0;" : "+l"(d) : "l"(a), "l"(b));
}

// ---------------- persistent scratch (no allocs allowed) ----------------
static __device__ float g_bufA[16777216];   // max: (16,64,128,128)
static __device__ float g_bufB[17040384];   // max: (16,64,129,129)
static __device__ float g_part[8388608];    // split-K partials

static __device__ float g_style0[NB * 256];
static __device__ float g_style1[NB * 128];
static __device__ float g_style2[NB * 128];
static __device__ float g_style3[NB * 64];
static __device__ float g_style4[NB * 64];
static __device__ float g_stylef[NB * 32];

static __device__ float g_demod0[NB * 128];
static __device__ float g_demod1[NB * 128];
static __device__ float g_demod2[NB * 64];
static __device__ float g_demod3[NB * 64];
static __device__ float g_demod4[NB * 32];

__device__ __forceinline__ float* style_ptr(int id) {
    switch (id) {
        case 0: return g_style0;
        case 1: return g_style1;
        case 2: return g_style2;
        case 3: return g_style3;
        case 4: return g_style4;
        default: return g_stylef;
    }
}
__device__ __forceinline__ float* demod_ptr(int id) {
    switch (id) {
        case 0: return g_demod0;
        case 1: return g_demod1;
        case 2: return g_demod2;
        case 3: return g_demod3;
        default: return g_demod4;
    }
}

struct P6 { const float* a[6]; };
struct P5 { const float* a[5]; };

// ---------------- fused style kernel: all 6 layers ----------------
__global__ void style_all_kernel(const float* __restrict__ z, P6 mw, P6 mb) {
    int gw = blockIdx.x * 8 + (threadIdx.x >> 5);
    int lane = threadIdx.x & 31;
    if (gw >= NB * 672) return;
    int b = gw / 672;
    int c = gw - b * 672;
    int L, ci, Ci;
    if (c < 256)      { L = 0; ci = c;       Ci = 256; }
    else if (c < 384) { L = 1; ci = c - 256; Ci = 128; }
    else if (c < 512) { L = 2; ci = c - 384; Ci = 128; }
    else if (c < 576) { L = 3; ci = c - 512; Ci = 64; }
    else if (c < 640) { L = 4; ci = c - 576; Ci = 64; }
    else              { L = 5; ci = c - 640; Ci = 32; }
    const float* zr = z + b * SDIM;
    const float* mr = mw.a[L] + (size_t)ci * SDIM;
    float s = 0.f;
#pragma unroll 4
    for (int k = lane; k < SDIM; k += 32) s += zr[k] * mr[k];
#pragma unroll
    for (int o = 16; o; o >>= 1) s += __shfl_xor_sync(0xffffffffu, s, o);
    if (lane == 0)
        style_ptr(L)[b * Ci + ci] = s * 0.04419417382415922f + mb.a[L][ci];
}

// ---------------- fused demod kernel, wsq inline ----------------
__global__ void demod_all_kernel(P5 w) {
    int gw = blockIdx.x * 8 + (threadIdx.x >> 5);
    int lane = threadIdx.x & 31;
    if (gw >= NB * 416) return;
    int b = gw / 416;
    int c = gw - b * 416;
    int L, co, Co, Ci;
    if (c < 128)      { L = 0; co = c;       Co = 128; Ci = 256; }
    else if (c < 256) { L = 1; co = c - 128; Co = 128; Ci = 128; }
    else if (c < 320) { L = 2; co = c - 256; Co = 64;  Ci = 128; }
    else if (c < 384) { L = 3; co = c - 320; Co = 64;  Ci = 64; }
    else              { L = 4; co = c - 384; Co = 32;  Ci = 64; }
    const float* st = style_ptr(L) + b * Ci;
    const float* wb = w.a[L] + (size_t)co * Ci * 9;
    float s = 0.f;
    for (int ci = lane; ci < Ci; ci += 32) {
        const float* p = wb + ci * 9;
        float wq = 0.f;
#pragma unroll
        for (int t = 0; t < 9; t++) wq += p[t] * p[t];
        float sv = st[ci];
        s += sv * sv * wq;
    }
#pragma unroll
    for (int o = 16; o; o >>= 1) s += __shfl_xor_sync(0xffffffffu, s, o);
    if (lane == 0)
        demod_ptr(L)[b * Co + co] = rsqrtf(s * (1.0f / (float)(Ci * 9)) + 1e-8f);
}

// ---------------- compose: bufA = (fg + (1-mask)*bg) * style0 ----------------
__global__ void compose_kernel(const float* __restrict__ fg,
                               const float* __restrict__ mask,
                               const float* __restrict__ bg) {
    int idx = blockIdx.x * blockDim.x + threadIdx.x;
    int p = idx & 1023;
    int c = (idx >> 10) & 255;
    int b = idx >> 18;
    float m = 1.0f - mask[b * 1024 + p];
    float v = fg[idx] + m * bg[idx];
    g_bufA[idx] = v * g_style0[b * 256 + c];
}

// ---------------- 3x3 conv, pad 1, f32x2; weight LDS.128; split-K -----------
// W_LD = 36: weight rows 16B-aligned -> both jp pairs per tap in ONE LDS.128.
template <int CIN_TOT, int CIN_DO, int COUT, int H, int W, bool SRC_A, int CO_T,
          int NSPLIT>
__global__ __launch_bounds__(256) void conv3x3_kernel(const float* __restrict__ wraw,
                                                      const float* __restrict__ bias,
                                                      int demod_id, int style_id) {
    static_assert(CO_T == 32, "inner loop specialized for CO_T=32");
    constexpr int CI_T = 8, TH = 8, TW = 32;
    constexpr int IN_LD = 36;
    constexpr int W_LD = 36;       // 16B-aligned weight rows (144 B)
    constexpr int TILES_X = W / TW;
    __shared__ __align__(16) float s_in[TH + 2][CI_T + 1][IN_LD];
    __shared__ __align__(16) float s_w[CI_T][9][W_LD];

    const float* in = SRC_A ? g_bufA : g_bufB;
    float* out = SRC_A ? g_bufB : g_bufA;
    const float* demod = demod_ptr(demod_id);
    const float* styn = style_ptr(style_id);

    int tid = threadIdx.x;
    int tile = blockIdx.x;
    int tx0 = (tile % TILES_X) * TW;
    int ty0 = (tile / TILES_X) * TH;
    int co_base = blockIdx.y * CO_T;

    int b = blockIdx.z / NSPLIT;
    int half = blockIdx.z % NSPLIT;
    int cin_off = half * CIN_DO;

    int warp = tid >> 5;
    int lane = tid & 31;
    int r = lane >> 2;
    int c0 = (lane & 3) << 3;

    ull acc[2][8];
#pragma unroll
    for (int jp = 0; jp < 2; jp++)
#pragma unroll
        for (int p = 0; p < 8; p++) acc[jp][p] = 0ull;

    const float wscale = rsqrtf((float)(CIN_TOT * 9));
    const float* in_b = in + (size_t)b * CIN_TOT * H * W;

    int colA = tid & 31;
    int gxA = tx0 + colA - 1;
    bool gxA_ok = (gxA >= 0 && gxA < W);
    int ixB = 32 + (tid & 1);
    int rowB = tid >> 1;
    int iyB = rowB >> 3, ciB = rowB & 7;
    int gxB = tx0 + ixB - 1;
    int gyB = ty0 + iyB - 1;
    bool B_ok = (tid < 160) && gxB >= 0 && gxB < W && gyB >= 0 && gyB < H;

    for (int cb = 0; cb < CIN_DO; cb += CI_T) {
        __syncthreads();
        const float* in_c = in_b + (size_t)(cin_off + cb) * H * W;
#pragma unroll
        for (int k = 0; k < 10; k++) {
            int rowq = (tid + k * 256) >> 5;
            int iy = rowq >> 3;
            int ci = rowq & 7;
            int gy = ty0 + iy - 1;
            float v = 0.f;
            if (gy >= 0 && gy < H && gxA_ok)
                v = in_c[ci * H * W + gy * W + gxA];
            s_in[iy][ci][colA] = v;
        }
        {
            float v = 0.f;
            if (B_ok) v = in_c[ciB * H * W + gyB * W + gxB];
            if (tid < 160) s_in[iyB][ciB][ixB] = v;
        }
#pragma unroll
        for (int k = 0; k < 9; k++) {
            int idx = tid + k * 256;
            int co = idx / (CI_T * 9);
            int rem = idx % (CI_T * 9);
            int ci = rem / 9, tap = rem % 9;
            s_w[ci][tap][co] =
                wraw[((size_t)(co_base + co) * CIN_TOT + cin_off + cb + ci) * 9 +
                     tap] * wscale;
        }
        __syncthreads();
#pragma unroll
        for (int ci = 0; ci < CI_T; ci++) {
#pragma unroll
            for (int ky = 0; ky < 3; ky++) {
                const float4* row4 =
                    reinterpret_cast<const float4*>(&s_in[r + ky][ci][c0]);
                float4 q0 = row4[0];
                float4 q1 = row4[1];
                float4 q2 = row4[2];
                ull xd[10];
                xd[0] = pack2(q0.x, q0.x); xd[1] = pack2(q0.y, q0.y);
                xd[2] = pack2(q0.z, q0.z); xd[3] = pack2(q0.w, q0.w);
                xd[4] = pack2(q1.x, q1.x); xd[5] = pack2(q1.y, q1.y);
                xd[6] = pack2(q1.z, q1.z); xd[7] = pack2(q1.w, q1.w);
                xd[8] = pack2(q2.x, q2.x); xd[9] = pack2(q2.y, q2.y);
#pragma unroll
                for (int kx = 0; kx < 3; kx++) {
                    // one LDS.128 fetches both jp weight pairs
                    float4 wq4 = *reinterpret_cast<const float4*>(
                        &s_w[ci][ky * 3 + kx][warp * 4]);
                    ull w2a = pack2(wq4.x, wq4.y);
                    ull w2b = pack2(wq4.z, wq4.w);
#pragma unroll
                    for (int p = 0; p < 8; p++) ffma2(acc[0][p], w2a, xd[kx + p]);
#pragma unroll
                    for (int p = 0; p < 8; p++) ffma2(acc[1][p], w2b, xd[kx + p]);
                }
            }
        }
    }
    int oy = ty0 + r;
#pragma unroll
    for (int jp = 0; jp < 2; jp++) {
        float vlo[8], vhi[8];
#pragma unroll
        for (int p = 0; p < 8; p++) unpack2(acc[jp][p], vlo[p], vhi[p]);
#pragma unroll
        for (int h = 0; h < 2; h++) {
            int co = co_base + warp * 4 + jp * 2 + h;
            const float* src = h ? vhi : vlo;
            if (NSPLIT > 1) {
                float* pp = g_part +
                            (((size_t)half * NB + b) * COUT + co) * H * W +
                            oy * W + tx0 + c0;
                float4 o0, o1;
                o0.x = src[0]; o0.y = src[1]; o0.z = src[2]; o0.w = src[3];
                o1.x = src[4]; o1.y = src[5]; o1.z = src[6]; o1.w = src[7];
                reinterpret_cast<float4*>(pp)[0] = o0;
                reinterpret_cast<float4*>(pp)[1] = o1;
            } else {
                float dm = demod[b * COUT + co];
                float bi = bias[co];
                float sn = styn[b * COUT + co];
                float* op = out + (size_t)b * COUT * H * W +
                            (size_t)co * H * W + oy * W + tx0 + c0;
                float4 o0, o1;
                float vv[8];
#pragma unroll
                for (int p = 0; p < 8; p++) {
                    float v = src[p] * dm + bi;
                    vv[p] = (v > 0.f ? v : 0.2f * v) * 1.41421356237309515f * sn;
                }
                o0.x = vv[0]; o0.y = vv[1]; o0.z = vv[2]; o0.w = vv[3];
                o1.x = vv[4]; o1.y = vv[5]; o1.z = vv[6]; o1.w = vv[7];
                reinterpret_cast<float4*>(op)[0] = o0;
                reinterpret_cast<float4*>(op)[1] = o1;
            }
        }
    }
}

// ---------------- split-K combine ----------------
template <int CO, int HW, int NHALF, bool DST_B>
__global__ void combine_kernel(const float* __restrict__ bias,
                               int demod_id, int style_id) {
    int idx = blockIdx.x * blockDim.x + threadIdx.x;
    constexpr int COHW = CO * HW;
    int b = idx / COHW;
    int co = (idx / HW) & (CO - 1);
    float p = 0.f;
#pragma unroll
    for (int h = 0; h < NHALF; h++) p += g_part[idx + (size_t)h * NB * COHW];
    float v = p * demod_ptr(demod_id)[b * CO + co] + bias[co];
    v = (v > 0.f ? v : 0.2f * v) * 1.41421356237309515f *
        style_ptr(style_id)[b * CO + co];
    (DST_B ? g_bufB : g_bufA)[idx] = v;
}

// ---------------- transposed conv: dense interior (R12 winner) --------------
template <int CIN, int COUT, int HIN, bool SRC_A>
__global__ __launch_bounds__(256) void tconv_kernel(const float* __restrict__ wraw,
                                                    int demod_id) {
    constexpr int HOUT = 2 * HIN + 1;
    constexpr int CO_T = 32, CI_T = 8, TH = 8, TW = 32;
    constexpr int IR = 6, ICW = 18, IC_LD = 19;
    constexpr int W_LD = 34;
    constexpr int TILES_X = (2 * HIN) / TW;
    __shared__ __align__(16) float s_in[CI_T][IR][IC_LD];
    __shared__ __align__(16) float s_w[CI_T][9][W_LD];

    const float* in = SRC_A ? g_bufA : g_bufB;
    float* out = SRC_A ? g_bufB : g_bufA;
    const float* demod = demod_ptr(demod_id);

    int tid = threadIdx.x;
    int tile = blockIdx.x;
    int tx0 = (tile % TILES_X) * TW;
    int ty0 = (tile / TILES_X) * TH;
    int co_base = blockIdx.y * CO_T;
    int b = blockIdx.z;

    int co_grp = tid >> 6;
    int lane = tid & 31;
    int wrp = tid >> 5;
    int r = 2 * ((lane >> 3) & 3) + (wrp & 1);
    int c0 = (lane & 7) << 2;
    int h = c0 >> 1;

    int iy_base = (ty0 >> 1) - 1;
    int jx_base = (tx0 >> 1) - 1;

    ull acc[4][4];
#pragma unroll
    for (int jp = 0; jp < 4; jp++)
#pragma unroll
        for (int p = 0; p < 4; p++) acc[jp][p] = 0ull;

    const float wscale = rsqrtf((float)(CIN * 9));
    const float* in_b = in + (size_t)b * CIN * HIN * HIN;

    for (int cb = 0; cb < CIN; cb += CI_T) {
        __syncthreads();
        for (int idx = tid; idx < CI_T * IR * ICW; idx += 256) {
            int ci = idx / (IR * ICW);
            int rem = idx % (IR * ICW);
            int iy = rem / ICW, ix = rem % ICW;
            int gy = iy_base + iy, gx = jx_base + ix;
            float v = 0.f;
            if (gy >= 0 && gy < HIN && gx >= 0 && gx < HIN)
                v = in_b[(size_t)(cb + ci) * HIN * HIN + gy * HIN + gx];
            s_in[ci][iy][ix] = v;
        }
        for (int idx = tid; idx < CO_T * CI_T * 9; idx += 256) {
            int co = idx / (CI_T * 9);
            int rem = idx % (CI_T * 9);
            int ci = rem / 9, tap = rem % 9;
            s_w[ci][tap][co] =
                wraw[((size_t)(co_base + co) * CIN + cb + ci) * 9 + tap] * wscale;
        }
        __syncthreads();
#pragma unroll
        for (int ci = 0; ci < CI_T; ci++) {
            int ky0 = r & 1;
            for (int ky = ky0; ky < 3; ky += 2) {
                int ir = ((r + ky - 2) >> 1) + 1;
                float x0v = s_in[ci][ir][h];
                float x1v = s_in[ci][ir][h + 1];
                float x2v = s_in[ci][ir][h + 2];
                ull xd0 = pack2(x0v, x0v);
                ull xd1 = pack2(x1v, x1v);
                ull xd2 = pack2(x2v, x2v);
                int wr = (2 - ky) * 3;
#pragma unroll
                for (int jp = 0; jp < 4; jp++) {
                    int co = co_grp * 8 + jp * 2;
                    ull w0 = *reinterpret_cast<const ull*>(&s_w[ci][wr + 0][co]);
                    ull w1 = *reinterpret_cast<const ull*>(&s_w[ci][wr + 1][co]);
                    ull w2 = *reinterpret_cast<const ull*>(&s_w[ci][wr + 2][co]);
                    ffma2(acc[jp][0], w2, xd0);
                    ffma2(acc[jp][0], w0, xd1);
                    ffma2(acc[jp][1], w1, xd1);
                    ffma2(acc[jp][2], w2, xd1);
                    ffma2(acc[jp][2], w0, xd2);
                    ffma2(acc[jp][3], w1, xd2);
                }
            }
        }
    }
    int oy = ty0 + r;
    float* out_b = out + (size_t)b * COUT * HOUT * HOUT;
#pragma unroll
    for (int jp = 0; jp < 4; jp++) {
#pragma unroll
        for (int hh = 0; hh < 2; hh++) {
            int co = co_base + co_grp * 8 + jp * 2 + hh;
            float dm = demod[b * COUT + co];
#pragma unroll
            for (int p = 0; p < 4; p++) {
                float lo, hi;
                unpack2(acc[jp][p], lo, hi);
                out_b[(size_t)co * HOUT * HOUT + oy * HOUT + tx0 + c0 + p] =
                    (hh ? hi : lo) * dm;
            }
        }
    }
}

// ---------------- tconv edge strips (unchanged R12 winner) ------------------
template <int CIN, int COUT, int HIN, bool SRC_A>
__global__ __launch_bounds__(256) void tconv_edge_kernel(
    const float* __restrict__ wraw, int demod_id) {
    constexpr int HOUT = 2 * HIN + 1;
    __shared__ float s_line[CIN][HIN];
    __shared__ float s_w3[CIN][3][33];

    const float* in = SRC_A ? g_bufA : g_bufB;
    float* out = SRC_A ? g_bufB : g_bufA;

    int s = blockIdx.y;
    int co_base = blockIdx.x * 32;
    int b = blockIdx.z;
    int tid = threadIdx.x;
    const float* in_b = in + (size_t)b * CIN * HIN * HIN;

    for (int e = tid; e < CIN * HIN; e += 256) {
        int ci = e / HIN, t = e % HIN;
        s_line[ci][t] = (s == 0)
            ? in_b[(size_t)ci * HIN * HIN + t * HIN + (HIN - 1)]
            : in_b[(size_t)ci * HIN * HIN + (HIN - 1) * HIN + t];
    }
    const float wscale = rsqrtf((float)(CIN * 9));
    for (int e = tid; e < 32 * CIN * 3; e += 256) {
        int co = e / (CIN * 3);
        int rem = e % (CIN * 3);
        int ci = rem / 3, k = rem % 3;
        int widx = (s == 0) ? ((2 - k) * 3 + 2) : (2 * 3 + (2 - k));
        s_w3[ci][k][co] =
            wraw[((size_t)(co_base + co) * CIN + ci) * 9 + widx] * wscale;
    }
    __syncthreads();

    int co = tid & 31;
    float dm = demod_ptr(demod_id)[b * COUT + co_base + co];
    float* out_b = out + ((size_t)b * COUT + co_base + co) * HOUT * HOUT;
    int nmax = HOUT - s;
    for (int n = tid >> 5; n < nmax; n += 8) {
        float acc = 0.f;
        if (n & 1) {
            int iy = (n - 1) >> 1;
#pragma unroll 4
            for (int ci = 0; ci < CIN; ci++)
                acc += s_line[ci][iy] * s_w3[ci][1][co];
        } else {
            int hh = n >> 1;
            if (hh >= 1) {
#pragma unroll 4
                for (int ci = 0; ci < CIN; ci++)
                    acc += s_line[ci][hh - 1] * s_w3[ci][0][co];
            }
            if (hh < HIN) {
#pragma unroll 4
                for (int ci = 0; ci < CIN; ci++)
                    acc += s_line[ci][hh] * s_w3[ci][2][co];
            }
        }
        acc *= dm;
        if (s == 0) out_b[n * HOUT + (HOUT - 1)] = acc;
        else out_b[(HOUT - 1) * HOUT + n] = acc;
    }
}

// ---------------- 4x4 blur + bias + leaky*sqrt2*style_next ----------------
template <int C, int HIN, bool SRC_A>
__global__ __launch_bounds__(256) void blur_kernel(const float* __restrict__ bias,
                                                   int style_id) {
    constexpr int HOUT = HIN - 1;
    constexpr int TH = 16, TW = 32;
    constexpr int TILES_X = HOUT / TW;
    __shared__ float s[TH + 3][TW + 4];

    const float* in = SRC_A ? g_bufA : g_bufB;
    float* out = SRC_A ? g_bufB : g_bufA;

    int tile = blockIdx.x;
    int x0 = (tile % TILES_X) * TW;
    int y0 = (tile / TILES_X) * TH;
    int c = blockIdx.y, b = blockIdx.z;
    const float* ip = in + ((size_t)b * C + c) * HIN * HIN;

    for (int idx = threadIdx.x; idx < (TH + 3) * (TW + 3); idx += 256) {
        int iy = idx / (TW + 3), ix = idx % (TW + 3);
        int gy = y0 + iy - 1, gx = x0 + ix - 1;
        float v = 0.f;
        if (gy >= 0 && gy < HIN && gx >= 0 && gx < HIN) v = ip[gy * HIN + gx];
        s[iy][ix] = v;
    }
    __syncthreads();

    const float c4[4] = {0.25f, 0.75f, 0.75f, 0.25f};
    float bi = bias[c];
    float sn = style_ptr(style_id)[b * C + c];
    float* op = out + ((size_t)b * C + c) * HOUT * HOUT;
#pragma unroll
    for (int q = 0; q < 2; q++) {
        int px = threadIdx.x + q * 256;
        int ly = px >> 5, lx = px & 31;
        float a = 0.f;
#pragma unroll
        for (int ky = 0; ky < 4; ky++) {
            float rs = 0.f;
#pragma unroll
            for (int kx = 0; kx < 4; kx++) rs += c4[kx] * s[ly + ky][lx + kx];
            a += c4[ky] * rs;
        }
        a += bi;
        a = (a > 0.f ? a : 0.2f * a) * 1.41421356237309515f * sn;
        op[(y0 + ly) * HOUT + x0 + lx] = a;
    }
}

// ---------------- final 1x1 (32 -> 3 of 4 ch), + out_bias ----------------
__global__ void final_kernel(const float* __restrict__ finw,
                             const float* __restrict__ outb,
                             float* __restrict__ out) {
    int idx = blockIdx.x * blockDim.x + threadIdx.x;
    int b = idx >> 14;
    int p = idx & 16383;
    const float* ib = g_bufB + (size_t)b * 32 * 16384 + p;
    float a0 = 0.f, a1 = 0.f, a2 = 0.f;
#pragma unroll
    for (int ci = 0; ci < 32; ci++) {
        float v = ib[(size_t)ci * 16384];
        a0 = fmaf(finw[ci], v, a0);
        a1 = fmaf(finw[32 + ci], v, a1);
        a2 = fmaf(finw[64 + ci], v, a2);
    }
    const float sc = rsqrtf(32.0f);
    out[(size_t)b * 3 * 16384 + p] = a0 * sc + outb[0];
    out[(size_t)b * 3 * 16384 + 16384 + p] = a1 * sc + outb[1];
    out[(size_t)b * 3 * 16384 + 2 * 16384 + p] = a2 * sc + outb[2];
}

// ------------------------------------------------------------------------
extern "C" void kernel_launch(void* const* d_in, const int* in_sizes, int n_in,
                              void* d_out, int out_size) {
    (void)in_sizes; (void)n_in; (void)out_size;
    const float* fg = (const float*)d_in[0];
    const float* mask = (const float*)d_in[1];
    const float* bg = (const float*)d_in[2];
    const float* z = (const float*)d_in[3];
    const float* l_w[5]  = {(const float*)d_in[4],  (const float*)d_in[8],
                            (const float*)d_in[12], (const float*)d_in[16],
                            (const float*)d_in[20]};
    const float* l_mw[5] = {(const float*)d_in[5],  (const float*)d_in[9],
                            (const float*)d_in[13], (const float*)d_in[17],
                            (const float*)d_in[21]};
    const float* l_mb[5] = {(const float*)d_in[6],  (const float*)d_in[10],
                            (const float*)d_in[14], (const float*)d_in[18],
                            (const float*)d_in[22]};
    const float* l_b[5]  = {(const float*)d_in[7],  (const float*)d_in[11],
                            (const float*)d_in[15], (const float*)d_in[19],
                            (const float*)d_in[23]};
    const float* finw = (const float*)d_in[24];
    const float* fin_mw = (const float*)d_in[25];
    const float* fin_mb = (const float*)d_in[26];
    const float* outb = (const float*)d_in[27];

    // fused setup: 2 kernels
    P6 mw6, mb6;
    for (int l = 0; l < 5; l++) { mw6.a[l] = l_mw[l]; mb6.a[l] = l_mb[l]; }
    mw6.a[5] = fin_mw; mb6.a[5] = fin_mb;
    style_all_kernel<<<1344, 256>>>(z, mw6, mb6);
    P5 w5;
    for (int l = 0; l < 5; l++) w5.a[l] = l_w[l];
    demod_all_kernel<<<832, 256>>>(w5);

    // compose + modulate for layer 0 -> bufA
    compose_kernel<<<(NB * 256 * 1024) / 256, 256>>>(fg, mask, bg);

    // l0: 256->128 @32x32, split-K=4 -> 1024 CTAs
    conv3x3_kernel<256, 64, 128, 32, 32, true, 32, 4>
        <<<dim3(4, 4, 64), 256>>>(l_w[0], l_b[0], 0, 1);
    combine_kernel<128, 1024, 4, true><<<8192, 256>>>(l_b[0], 0, 1);
    // l1: tconv 128->128, 32 -> 65 (B -> A): dense 64x64 interior + edges
    tconv_kernel<128, 128, 32, false><<<dim3(16, 4, NB), 256>>>(l_w[1], 1);
    tconv_edge_kernel<128, 128, 32, false><<<dim3(4, 2, NB), 256>>>(l_w[1], 1);
    // blur 65 -> 64 + act + style2   (A -> B)
    blur_kernel<128, 65, true><<<dim3(8, 128, NB), 256>>>(l_b[1], 2);
    // l2: 128->64 @64x64, split-K=2 -> 1024 CTAs
    conv3x3_kernel<128, 64, 64, 64, 64, false, 32, 2>
        <<<dim3(16, 2, 32), 256>>>(l_w[2], l_b[2], 2, 3);
    combine_kernel<64, 4096, 2, false><<<16384, 256>>>(l_b[2], 2, 3);
    // l3: tconv 64->64, 64 -> 129 (A -> B): dense 128x128 interior + edges
    tconv_kernel<64, 64, 64, true><<<dim3(64, 2, NB), 256>>>(l_w[3], 3);
    tconv_edge_kernel<64, 64, 64, true><<<dim3(2, 2, NB), 256>>>(l_w[3], 3);
    // blur 129 -> 128 + act + style4   (B -> A)
    blur_kernel<64, 129, false><<<dim3(32, 64, NB), 256>>>(l_b[3], 4);
    // l4: 64->32 @128x128   (A -> B)
    conv3x3_kernel<64, 64, 32, 128, 128, true, 32, 1>
        <<<dim3(64, 1, 16), 256>>>(l_w[4], l_b[4], 4, 5);
    // final 1x1 32->3 + out_bias   (B -> d_out)
    final_kernel<<<(NB * 16384) / 256, 256>>>(finw, outb, (float*)d_out);
}

// round 16
// speedup vs baseline: 1.0265x; 1.0188x over previous
#include <cuda_runtime.h>
#include <math.h>

#define NB 16
#define SDIM 512

typedef unsigned long long ull;

__device__ __forceinline__ ull pack2(float a, float b) {
    ull r;
    asm("mov.b64 %0, {%1, %2};" : "=l"(r) : "f"(a), "f"(b));
    return r;
}
__device__ __forceinline__ void unpack2(ull v, float& a, float& b) {
    asm("mov.b64 {%0, %1}, %2;" : "=f"(a), "=f"(b) : "l"(v));
}
__device__ __forceinline__ void ffma2(ull& d, ull a, ull b) {
    asm("fma.rn.f32x2 %0, %1, %2, %0;" : "+l"(d) : "l"(a), "l"(b));
}

// ---------------- persistent scratch (no allocs allowed) ----------------
static __device__ float g_bufA[16777216];   // max: (16,64,128,128)
static __device__ float g_bufB[17040384];   // max: (16,64,129,129)
static __device__ float g_part[8388608];    // split-K partials

static __device__ float g_style0[NB * 256];
static __device__ float g_style1[NB * 128];
static __device__ float g_style2[NB * 128];
static __device__ float g_style3[NB * 64];
static __device__ float g_style4[NB * 64];
static __device__ float g_stylef[NB * 32];

static __device__ float g_demod0[NB * 128];
static __device__ float g_demod1[NB * 128];
static __device__ float g_demod2[NB * 64];
static __device__ float g_demod3[NB * 64];
static __device__ float g_demod4[NB * 32];

__device__ __forceinline__ float* style_ptr(int id) {
    switch (id) {
        case 0: return g_style0;
        case 1: return g_style1;
        case 2: return g_style2;
        case 3: return g_style3;
        case 4: return g_style4;
        default: return g_stylef;
    }
}
__device__ __forceinline__ float* demod_ptr(int id) {
    switch (id) {
        case 0: return g_demod0;
        case 1: return g_demod1;
        case 2: return g_demod2;
        case 3: return g_demod3;
        default: return g_demod4;
    }
}

struct P6 { const float* a[6]; };
struct P5 { const float* a[5]; };

// ---------------- fused style kernel: all 6 layers ----------------
__global__ void style_all_kernel(const float* __restrict__ z, P6 mw, P6 mb) {
    int gw = blockIdx.x * 8 + (threadIdx.x >> 5);
    int lane = threadIdx.x & 31;
    if (gw >= NB * 672) return;
    int b = gw / 672;
    int c = gw - b * 672;
    int L, ci, Ci;
    if (c < 256)      { L = 0; ci = c;       Ci = 256; }
    else if (c < 384) { L = 1; ci = c - 256; Ci = 128; }
    else if (c < 512) { L = 2; ci = c - 384; Ci = 128; }
    else if (c < 576) { L = 3; ci = c - 512; Ci = 64; }
    else if (c < 640) { L = 4; ci = c - 576; Ci = 64; }
    else              { L = 5; ci = c - 640; Ci = 32; }
    const float* zr = z + b * SDIM;
    const float* mr = mw.a[L] + (size_t)ci * SDIM;
    float s = 0.f;
#pragma unroll 4
    for (int k = lane; k < SDIM; k += 32) s += zr[k] * mr[k];
#pragma unroll
    for (int o = 16; o; o >>= 1) s += __shfl_xor_sync(0xffffffffu, s, o);
    if (lane == 0)
        style_ptr(L)[b * Ci + ci] = s * 0.04419417382415922f + mb.a[L][ci];
}

// ---------------- fused demod kernel, wsq inline ----------------
__global__ void demod_all_kernel(P5 w) {
    int gw = blockIdx.x * 8 + (threadIdx.x >> 5);
    int lane = threadIdx.x & 31;
    if (gw >= NB * 416) return;
    int b = gw / 416;
    int c = gw - b * 416;
    int L, co, Co, Ci;
    if (c < 128)      { L = 0; co = c;       Co = 128; Ci = 256; }
    else if (c < 256) { L = 1; co = c - 128; Co = 128; Ci = 128; }
    else if (c < 320) { L = 2; co = c - 256; Co = 64;  Ci = 128; }
    else if (c < 384) { L = 3; co = c - 320; Co = 64;  Ci = 64; }
    else              { L = 4; co = c - 384; Co = 32;  Ci = 64; }
    const float* st = style_ptr(L) + b * Ci;
    const float* wb = w.a[L] + (size_t)co * Ci * 9;
    float s = 0.f;
    for (int ci = lane; ci < Ci; ci += 32) {
        const float* p = wb + ci * 9;
        float wq = 0.f;
#pragma unroll
        for (int t = 0; t < 9; t++) wq += p[t] * p[t];
        float sv = st[ci];
        s += sv * sv * wq;
    }
#pragma unroll
    for (int o = 16; o; o >>= 1) s += __shfl_xor_sync(0xffffffffu, s, o);
    if (lane == 0)
        demod_ptr(L)[b * Co + co] = rsqrtf(s * (1.0f / (float)(Ci * 9)) + 1e-8f);
}

// ---------------- compose (float4): bufA = (fg + (1-mask)*bg) * style0 ------
__global__ void compose_kernel(const float* __restrict__ fg,
                               const float* __restrict__ mask,
                               const float* __restrict__ bg) {
    int idx4 = blockIdx.x * blockDim.x + threadIdx.x;  // over 16*256*256
    int p4 = idx4 & 255;
    int c = (idx4 >> 8) & 255;
    int b = idx4 >> 16;
    float4 m4 = reinterpret_cast<const float4*>(mask)[b * 256 + p4];
    float4 f4 = reinterpret_cast<const float4*>(fg)[idx4];
    float4 g4 = reinterpret_cast<const float4*>(bg)[idx4];
    float s = g_style0[b * 256 + c];
    float4 o;
    o.x = (f4.x + (1.f - m4.x) * g4.x) * s;
    o.y = (f4.y + (1.f - m4.y) * g4.y) * s;
    o.z = (f4.z + (1.f - m4.z) * g4.z) * s;
    o.w = (f4.w + (1.f - m4.w) * g4.w) * s;
    reinterpret_cast<float4*>(g_bufA)[idx4] = o;
}

// ---------------- 3x3 conv, pad 1, f32x2; shift/mask staging; split-K -------
// (exact R12 winner body)
template <int CIN_TOT, int CIN_DO, int COUT, int H, int W, bool SRC_A, int CO_T,
          int NSPLIT>
__global__ __launch_bounds__(256) void conv3x3_kernel(const float* __restrict__ wraw,
                                                      const float* __restrict__ bias,
                                                      int demod_id, int style_id) {
    constexpr int CI_T = 8, TH = 8, TW = 32;
    constexpr int CO_PW = CO_T / 8;
    constexpr int JP = CO_PW / 2;
    constexpr int IN_LD = 36;
    constexpr int W_LD = CO_T + 2;
    constexpr int TILES_X = W / TW;
    __shared__ __align__(16) float s_in[TH + 2][CI_T + 1][IN_LD];
    __shared__ __align__(16) float s_w[CI_T][9][W_LD];

    const float* in = SRC_A ? g_bufA : g_bufB;
    float* out = SRC_A ? g_bufB : g_bufA;
    const float* demod = demod_ptr(demod_id);
    const float* styn = style_ptr(style_id);

    int tid = threadIdx.x;
    int tile = blockIdx.x;
    int tx0 = (tile % TILES_X) * TW;
    int ty0 = (tile / TILES_X) * TH;
    int co_base = blockIdx.y * CO_T;

    int b = blockIdx.z / NSPLIT;
    int half = blockIdx.z % NSPLIT;
    int cin_off = half * CIN_DO;

    int warp = tid >> 5;
    int lane = tid & 31;
    int r = lane >> 2;
    int c0 = (lane & 3) << 3;

    ull acc[JP][8];
#pragma unroll
    for (int jp = 0; jp < JP; jp++)
#pragma unroll
        for (int p = 0; p < 8; p++) acc[jp][p] = 0ull;

    const float wscale = rsqrtf((float)(CIN_TOT * 9));
    const float* in_b = in + (size_t)b * CIN_TOT * H * W;

    int colA = tid & 31;
    int gxA = tx0 + colA - 1;
    bool gxA_ok = (gxA >= 0 && gxA < W);
    int ixB = 32 + (tid & 1);
    int rowB = tid >> 1;
    int iyB = rowB >> 3, ciB = rowB & 7;
    int gxB = tx0 + ixB - 1;
    int gyB = ty0 + iyB - 1;
    bool B_ok = (tid < 160) && gxB >= 0 && gxB < W && gyB >= 0 && gyB < H;

    for (int cb = 0; cb < CIN_DO; cb += CI_T) {
        __syncthreads();
        const float* in_c = in_b + (size_t)(cin_off + cb) * H * W;
#pragma unroll
        for (int k = 0; k < 10; k++) {
            int rowq = (tid + k * 256) >> 5;
            int iy = rowq >> 3;
            int ci = rowq & 7;
            int gy = ty0 + iy - 1;
            float v = 0.f;
            if (gy >= 0 && gy < H && gxA_ok)
                v = in_c[ci * H * W + gy * W + gxA];
            s_in[iy][ci][colA] = v;
        }
        {
            float v = 0.f;
            if (B_ok) v = in_c[ciB * H * W + gyB * W + gxB];
            if (tid < 160) s_in[iyB][ciB][ixB] = v;
        }
#pragma unroll
        for (int k = 0; k < 9; k++) {
            int idx = tid + k * 256;
            int co = idx / (CI_T * 9);
            int rem = idx % (CI_T * 9);
            int ci = rem / 9, tap = rem % 9;
            s_w[ci][tap][co] =
                wraw[((size_t)(co_base + co) * CIN_TOT + cin_off + cb + ci) * 9 +
                     tap] * wscale;
        }
        __syncthreads();
#pragma unroll
        for (int ci = 0; ci < CI_T; ci++) {
#pragma unroll
            for (int ky = 0; ky < 3; ky++) {
                const float4* row4 =
                    reinterpret_cast<const float4*>(&s_in[r + ky][ci][c0]);
                float4 q0 = row4[0];
                float4 q1 = row4[1];
                float4 q2 = row4[2];
                ull xd[10];
                xd[0] = pack2(q0.x, q0.x); xd[1] = pack2(q0.y, q0.y);
                xd[2] = pack2(q0.z, q0.z); xd[3] = pack2(q0.w, q0.w);
                xd[4] = pack2(q1.x, q1.x); xd[5] = pack2(q1.y, q1.y);
                xd[6] = pack2(q1.z, q1.z); xd[7] = pack2(q1.w, q1.w);
                xd[8] = pack2(q2.x, q2.x); xd[9] = pack2(q2.y, q2.y);
#pragma unroll
                for (int kx = 0; kx < 3; kx++) {
#pragma unroll
                    for (int jp = 0; jp < JP; jp++) {
                        ull w2 = *reinterpret_cast<const ull*>(
                            &s_w[ci][ky * 3 + kx][warp * CO_PW + jp * 2]);
#pragma unroll
                        for (int p = 0; p < 8; p++) ffma2(acc[jp][p], w2, xd[kx + p]);
                    }
                }
            }
        }
    }
    int oy = ty0 + r;
#pragma unroll
    for (int jp = 0; jp < JP; jp++) {
        float vlo[8], vhi[8];
#pragma unroll
        for (int p = 0; p < 8; p++) unpack2(acc[jp][p], vlo[p], vhi[p]);
#pragma unroll
        for (int h = 0; h < 2; h++) {
            int co = co_base + warp * CO_PW + jp * 2 + h;
            const float* src = h ? vhi : vlo;
            if (NSPLIT > 1) {
                float* pp = g_part +
                            (((size_t)half * NB + b) * COUT + co) * H * W +
                            oy * W + tx0 + c0;
                float4 o0, o1;
                o0.x = src[0]; o0.y = src[1]; o0.z = src[2]; o0.w = src[3];
                o1.x = src[4]; o1.y = src[5]; o1.z = src[6]; o1.w = src[7];
                reinterpret_cast<float4*>(pp)[0] = o0;
                reinterpret_cast<float4*>(pp)[1] = o1;
            } else {
                float dm = demod[b * COUT + co];
                float bi = bias[co];
                float sn = styn[b * COUT + co];
                float* op = out + (size_t)b * COUT * H * W +
                            (size_t)co * H * W + oy * W + tx0 + c0;
                float4 o0, o1;
                float vv[8];
#pragma unroll
                for (int p = 0; p < 8; p++) {
                    float v = src[p] * dm + bi;
                    vv[p] = (v > 0.f ? v : 0.2f * v) * 1.41421356237309515f * sn;
                }
                o0.x = vv[0]; o0.y = vv[1]; o0.z = vv[2]; o0.w = vv[3];
                o1.x = vv[4]; o1.y = vv[5]; o1.z = vv[6]; o1.w = vv[7];
                reinterpret_cast<float4*>(op)[0] = o0;
                reinterpret_cast<float4*>(op)[1] = o1;
            }
        }
    }
}

// ---------------- split-K combine (float4) ----------------
// indexed in float4 units; CO*HW/4 and HW/4 are powers of 2
template <int CO, int HW, int NHALF, bool DST_B>
__global__ void combine_kernel(const float* __restrict__ bias,
                               int demod_id, int style_id) {
    int idx4 = blockIdx.x * blockDim.x + threadIdx.x;   // over NB*CO*HW/4
    constexpr int COHW4 = CO * HW / 4;
    constexpr int HW4 = HW / 4;
    int b = idx4 / COHW4;
    int co = (idx4 / HW4) & (CO - 1);
    const float4* gp = reinterpret_cast<const float4*>(g_part);
    float4 p = gp[idx4];
#pragma unroll
    for (int h = 1; h < NHALF; h++) {
        float4 q = gp[idx4 + (size_t)h * NB * COHW4];
        p.x += q.x; p.y += q.y; p.z += q.z; p.w += q.w;
    }
    float dm = demod_ptr(demod_id)[b * CO + co];
    float bi = bias[co];
    float sn = style_ptr(style_id)[b * CO + co] * 1.41421356237309515f;
    float4 o;
    float v;
    v = p.x * dm + bi; o.x = (v > 0.f ? v : 0.2f * v) * sn;
    v = p.y * dm + bi; o.y = (v > 0.f ? v : 0.2f * v) * sn;
    v = p.z * dm + bi; o.z = (v > 0.f ? v : 0.2f * v) * sn;
    v = p.w * dm + bi; o.w = (v > 0.f ? v : 0.2f * v) * sn;
    reinterpret_cast<float4*>(DST_B ? g_bufB : g_bufA)[idx4] = o;
}

// ---------------- transposed conv: dense interior (R12 winner) --------------
template <int CIN, int COUT, int HIN, bool SRC_A>
__global__ __launch_bounds__(256) void tconv_kernel(const float* __restrict__ wraw,
                                                    int demod_id) {
    constexpr int HOUT = 2 * HIN + 1;
    constexpr int CO_T = 32, CI_T = 8, TH = 8, TW = 32;
    constexpr int IR = 6, ICW = 18, IC_LD = 19;
    constexpr int W_LD = 34;
    constexpr int TILES_X = (2 * HIN) / TW;
    __shared__ __align__(16) float s_in[CI_T][IR][IC_LD];
    __shared__ __align__(16) float s_w[CI_T][9][W_LD];

    const float* in = SRC_A ? g_bufA : g_bufB;
    float* out = SRC_A ? g_bufB : g_bufA;
    const float* demod = demod_ptr(demod_id);

    int tid = threadIdx.x;
    int tile = blockIdx.x;
    int tx0 = (tile % TILES_X) * TW;
    int ty0 = (tile / TILES_X) * TH;
    int co_base = blockIdx.y * CO_T;
    int b = blockIdx.z;

    int co_grp = tid >> 6;
    int lane = tid & 31;
    int wrp = tid >> 5;
    int r = 2 * ((lane >> 3) & 3) + (wrp & 1);
    int c0 = (lane & 7) << 2;
    int h = c0 >> 1;

    int iy_base = (ty0 >> 1) - 1;
    int jx_base = (tx0 >> 1) - 1;

    ull acc[4][4];
#pragma unroll
    for (int jp = 0; jp < 4; jp++)
#pragma unroll
        for (int p = 0; p < 4; p++) acc[jp][p] = 0ull;

    const float wscale = rsqrtf((float)(CIN * 9));
    const float* in_b = in + (size_t)b * CIN * HIN * HIN;

    for (int cb = 0; cb < CIN; cb += CI_T) {
        __syncthreads();
        for (int idx = tid; idx < CI_T * IR * ICW; idx += 256) {
            int ci = idx / (IR * ICW);
            int rem = idx % (IR * ICW);
            int iy = rem / ICW, ix = rem % ICW;
            int gy = iy_base + iy, gx = jx_base + ix;
            float v = 0.f;
            if (gy >= 0 && gy < HIN && gx >= 0 && gx < HIN)
                v = in_b[(size_t)(cb + ci) * HIN * HIN + gy * HIN + gx];
            s_in[ci][iy][ix] = v;
        }
        for (int idx = tid; idx < CO_T * CI_T * 9; idx += 256) {
            int co = idx / (CI_T * 9);
            int rem = idx % (CI_T * 9);
            int ci = rem / 9, tap = rem % 9;
            s_w[ci][tap][co] =
                wraw[((size_t)(co_base + co) * CIN + cb + ci) * 9 + tap] * wscale;
        }
        __syncthreads();
#pragma unroll
        for (int ci = 0; ci < CI_T; ci++) {
            int ky0 = r & 1;
            for (int ky = ky0; ky < 3; ky += 2) {
                int ir = ((r + ky - 2) >> 1) + 1;
                float x0v = s_in[ci][ir][h];
                float x1v = s_in[ci][ir][h + 1];
                float x2v = s_in[ci][ir][h + 2];
                ull xd0 = pack2(x0v, x0v);
                ull xd1 = pack2(x1v, x1v);
                ull xd2 = pack2(x2v, x2v);
                int wr = (2 - ky) * 3;
#pragma unroll
                for (int jp = 0; jp < 4; jp++) {
                    int co = co_grp * 8 + jp * 2;
                    ull w0 = *reinterpret_cast<const ull*>(&s_w[ci][wr + 0][co]);
                    ull w1 = *reinterpret_cast<const ull*>(&s_w[ci][wr + 1][co]);
                    ull w2 = *reinterpret_cast<const ull*>(&s_w[ci][wr + 2][co]);
                    ffma2(acc[jp][0], w2, xd0);
                    ffma2(acc[jp][0], w0, xd1);
                    ffma2(acc[jp][1], w1, xd1);
                    ffma2(acc[jp][2], w2, xd1);
                    ffma2(acc[jp][2], w0, xd2);
                    ffma2(acc[jp][3], w1, xd2);
                }
            }
        }
    }
    int oy = ty0 + r;
    float* out_b = out + (size_t)b * COUT * HOUT * HOUT;
#pragma unroll
    for (int jp = 0; jp < 4; jp++) {
#pragma unroll
        for (int hh = 0; hh < 2; hh++) {
            int co = co_base + co_grp * 8 + jp * 2 + hh;
            float dm = demod[b * COUT + co];
#pragma unroll
            for (int p = 0; p < 4; p++) {
                float lo, hi;
                unpack2(acc[jp][p], lo, hi);
                out_b[(size_t)co * HOUT * HOUT + oy * HOUT + tx0 + c0 + p] =
                    (hh ? hi : lo) * dm;
            }
        }
    }
}

// ---------------- tconv edge strips (unchanged R12 winner) ------------------
template <int CIN, int COUT, int HIN, bool SRC_A>
__global__ __launch_bounds__(256) void tconv_edge_kernel(
    const float* __restrict__ wraw, int demod_id) {
    constexpr int HOUT = 2 * HIN + 1;
    __shared__ float s_line[CIN][HIN];
    __shared__ float s_w3[CIN][3][33];

    const float* in = SRC_A ? g_bufA : g_bufB;
    float* out = SRC_A ? g_bufB : g_bufA;

    int s = blockIdx.y;
    int co_base = blockIdx.x * 32;
    int b = blockIdx.z;
    int tid = threadIdx.x;
    const float* in_b = in + (size_t)b * CIN * HIN * HIN;

    for (int e = tid; e < CIN * HIN; e += 256) {
        int ci = e / HIN, t = e % HIN;
        s_line[ci][t] = (s == 0)
            ? in_b[(size_t)ci * HIN * HIN + t * HIN + (HIN - 1)]
            : in_b[(size_t)ci * HIN * HIN + (HIN - 1) * HIN + t];
    }
    const float wscale = rsqrtf((float)(CIN * 9));
    for (int e = tid; e < 32 * CIN * 3; e += 256) {
        int co = e / (CIN * 3);
        int rem = e % (CIN * 3);
        int ci = rem / 3, k = rem % 3;
        int widx = (s == 0) ? ((2 - k) * 3 + 2) : (2 * 3 + (2 - k));
        s_w3[ci][k][co] =
            wraw[((size_t)(co_base + co) * CIN + ci) * 9 + widx] * wscale;
    }
    __syncthreads();

    int co = tid & 31;
    float dm = demod_ptr(demod_id)[b * COUT + co_base + co];
    float* out_b = out + ((size_t)b * COUT + co_base + co) * HOUT * HOUT;
    int nmax = HOUT - s;
    for (int n = tid >> 5; n < nmax; n += 8) {
        float acc = 0.f;
        if (n & 1) {
            int iy = (n - 1) >> 1;
#pragma unroll 4
            for (int ci = 0; ci < CIN; ci++)
                acc += s_line[ci][iy] * s_w3[ci][1][co];
        } else {
            int hh = n >> 1;
            if (hh >= 1) {
#pragma unroll 4
                for (int ci = 0; ci < CIN; ci++)
                    acc += s_line[ci][hh - 1] * s_w3[ci][0][co];
            }
            if (hh < HIN) {
#pragma unroll 4
                for (int ci = 0; ci < CIN; ci++)
                    acc += s_line[ci][hh] * s_w3[ci][2][co];
            }
        }
        acc *= dm;
        if (s == 0) out_b[n * HOUT + (HOUT - 1)] = acc;
        else out_b[(HOUT - 1) * HOUT + n] = acc;
    }
}

// ---------------- 4x4 blur + bias + leaky*sqrt2*style_next ----------------
template <int C, int HIN, bool SRC_A>
__global__ __launch_bounds__(256) void blur_kernel(const float* __restrict__ bias,
                                                   int style_id) {
    constexpr int HOUT = HIN - 1;
    constexpr int TH = 16, TW = 32;
    constexpr int TILES_X = HOUT / TW;
    __shared__ float s[TH + 3][TW + 4];

    const float* in = SRC_A ? g_bufA : g_bufB;
    float* out = SRC_A ? g_bufB : g_bufA;

    int tile = blockIdx.x;
    int x0 = (tile % TILES_X) * TW;
    int y0 = (tile / TILES_X) * TH;
    int c = blockIdx.y, b = blockIdx.z;
    const float* ip = in + ((size_t)b * C + c) * HIN * HIN;

    for (int idx = threadIdx.x; idx < (TH + 3) * (TW + 3); idx += 256) {
        int iy = idx / (TW + 3), ix = idx % (TW + 3);
        int gy = y0 + iy - 1, gx = x0 + ix - 1;
        float v = 0.f;
        if (gy >= 0 && gy < HIN && gx >= 0 && gx < HIN) v = ip[gy * HIN + gx];
        s[iy][ix] = v;
    }
    __syncthreads();

    const float c4[4] = {0.25f, 0.75f, 0.75f, 0.25f};
    float bi = bias[c];
    float sn = style_ptr(style_id)[b * C + c];
    float* op = out + ((size_t)b * C + c) * HOUT * HOUT;
#pragma unroll
    for (int q = 0; q < 2; q++) {
        int px = threadIdx.x + q * 256;
        int ly = px >> 5, lx = px & 31;
        float a = 0.f;
#pragma unroll
        for (int ky = 0; ky < 4; ky++) {
            float rs = 0.f;
#pragma unroll
            for (int kx = 0; kx < 4; kx++) rs += c4[kx] * s[ly + ky][lx + kx];
            a += c4[ky] * rs;
        }
        a += bi;
        a = (a > 0.f ? a : 0.2f * a) * 1.41421356237309515f * sn;
        op[(y0 + ly) * HOUT + x0 + lx] = a;
    }
}

// ---------------- final 1x1 (float4): 32 -> 3 of 4 ch, + out_bias -----------
__global__ void final_kernel(const float* __restrict__ finw,
                             const float* __restrict__ outb,
                             float* __restrict__ out) {
    int idx4 = blockIdx.x * blockDim.x + threadIdx.x;  // over 16*4096
    int b = idx4 >> 12;
    int p4 = idx4 & 4095;
    const float4* ib = reinterpret_cast<const float4*>(g_bufB) +
                       (size_t)b * 32 * 4096 + p4;
    float4 a0 = {0.f, 0.f, 0.f, 0.f};
    float4 a1 = {0.f, 0.f, 0.f, 0.f};
    float4 a2 = {0.f, 0.f, 0.f, 0.f};
#pragma unroll
    for (int ci = 0; ci < 32; ci++) {
        float4 v = ib[(size_t)ci * 4096];
        float w0 = finw[ci], w1 = finw[32 + ci], w2 = finw[64 + ci];
        a0.x = fmaf(w0, v.x, a0.x); a0.y = fmaf(w0, v.y, a0.y);
        a0.z = fmaf(w0, v.z, a0.z); a0.w = fmaf(w0, v.w, a0.w);
        a1.x = fmaf(w1, v.x, a1.x); a1.y = fmaf(w1, v.y, a1.y);
        a1.z = fmaf(w1, v.z, a1.z); a1.w = fmaf(w1, v.w, a1.w);
        a2.x = fmaf(w2, v.x, a2.x); a2.y = fmaf(w2, v.y, a2.y);
        a2.z = fmaf(w2, v.z, a2.z); a2.w = fmaf(w2, v.w, a2.w);
    }
    const float sc = rsqrtf(32.0f);
    float4* o4 = reinterpret_cast<float4*>(out) + (size_t)b * 3 * 4096;
    float4 o;
    o.x = a0.x * sc + outb[0]; o.y = a0.y * sc + outb[0];
    o.z = a0.z * sc + outb[0]; o.w = a0.w * sc + outb[0];
    o4[p4] = o;
    o.x = a1.x * sc + outb[1]; o.y = a1.y * sc + outb[1];
    o.z = a1.z * sc + outb[1]; o.w = a1.w * sc + outb[1];
    o4[4096 + p4] = o;
    o.x = a2.x * sc + outb[2]; o.y = a2.y * sc + outb[2];
    o.z = a2.z * sc + outb[2]; o.w = a2.w * sc + outb[2];
    o4[2 * 4096 + p4] = o;
}

// ------------------------------------------------------------------------
extern "C" void kernel_launch(void* const* d_in, const int* in_sizes, int n_in,
                              void* d_out, int out_size) {
    (void)in_sizes; (void)n_in; (void)out_size;
    const float* fg = (const float*)d_in[0];
    const float* mask = (const float*)d_in[1];
    const float* bg = (const float*)d_in[2];
    const float* z = (const float*)d_in[3];
    const float* l_w[5]  = {(const float*)d_in[4],  (const float*)d_in[8],
                            (const float*)d_in[12], (const float*)d_in[16],
                            (const float*)d_in[20]};
    const float* l_mw[5] = {(const float*)d_in[5],  (const float*)d_in[9],
                            (const float*)d_in[13], (const float*)d_in[17],
                            (const float*)d_in[21]};
    const float* l_mb[5] = {(const float*)d_in[6],  (const float*)d_in[10],
                            (const float*)d_in[14], (const float*)d_in[18],
                            (const float*)d_in[22]};
    const float* l_b[5]  = {(const float*)d_in[7],  (const float*)d_in[11],
                            (const float*)d_in[15], (const float*)d_in[19],
                            (const float*)d_in[23]};
    const float* finw = (const float*)d_in[24];
    const float* fin_mw = (const float*)d_in[25];
    const float* fin_mb = (const float*)d_in[26];
    const float* outb = (const float*)d_in[27];

    // fused setup: 2 kernels
    P6 mw6, mb6;
    for (int l = 0; l < 5; l++) { mw6.a[l] = l_mw[l]; mb6.a[l] = l_mb[l]; }
    mw6.a[5] = fin_mw; mb6.a[5] = fin_mb;
    style_all_kernel<<<1344, 256>>>(z, mw6, mb6);
    P5 w5;
    for (int l = 0; l < 5; l++) w5.a[l] = l_w[l];
    demod_all_kernel<<<832, 256>>>(w5);

    // compose + modulate for layer 0 -> bufA (float4)
    compose_kernel<<<(NB * 256 * 256) / 256, 256>>>(fg, mask, bg);

    // l0: 256->128 @32x32, split-K=4 -> 1024 CTAs
    conv3x3_kernel<256, 64, 128, 32, 32, true, 32, 4>
        <<<dim3(4, 4, 64), 256>>>(l_w[0], l_b[0], 0, 1);
    combine_kernel<128, 1024, 4, true><<<2048, 256>>>(l_b[0], 0, 1);
    // l1: tconv 128->128, 32 -> 65 (B -> A): dense 64x64 interior + edges
    tconv_kernel<128, 128, 32, false><<<dim3(16, 4, NB), 256>>>(l_w[1], 1);
    tconv_edge_kernel<128, 128, 32, false><<<dim3(4, 2, NB), 256>>>(l_w[1], 1);
    // blur 65 -> 64 + act + style2   (A -> B)
    blur_kernel<128, 65, true><<<dim3(8, 128, NB), 256>>>(l_b[1], 2);
    // l2: 128->64 @64x64, split-K=2 -> 1024 CTAs
    conv3x3_kernel<128, 64, 64, 64, 64, false, 32, 2>
        <<<dim3(16, 2, 32), 256>>>(l_w[2], l_b[2], 2, 3);
    combine_kernel<64, 4096, 2, false><<<4096, 256>>>(l_b[2], 2, 3);
    // l3: tconv 64->64, 64 -> 129 (A -> B): dense 128x128 interior + edges
    tconv_kernel<64, 64, 64, true><<<dim3(64, 2, NB), 256>>>(l_w[3], 3);
    tconv_edge_kernel<64, 64, 64, true><<<dim3(2, 2, NB), 256>>>(l_w[3], 3);
    // blur 129 -> 128 + act + style4   (B -> A)
    blur_kernel<64, 129, false><<<dim3(32, 64, NB), 256>>>(l_b[3], 4);
    // l4: 64->32 @128x128   (A -> B)
    conv3x3_kernel<64, 64, 32, 128, 128, true, 32, 1>
        <<<dim3(64, 1, 16), 256>>>(l_w[4], l_b[4], 4, 5);
    // final 1x1 32->3 + out_bias   (B -> d_out, float4)
    final_kernel<<<(NB * 4096) / 256, 256>>>(finw, outb, (float*)d_out);
}

// round 17
// speedup vs baseline: 1.0415x; 1.0146x over previous
#include <cuda_runtime.h>
#include <math.h>

#define NB 16
#define SDIM 512

typedef unsigned long long ull;

__device__ __forceinline__ ull pack2(float a, float b) {
    ull r;
    asm("mov.b64 %0, {%1, %2};" : "=l"(r) : "f"(a), "f"(b));
    return r;
}
__device__ __forceinline__ void unpack2(ull v, float& a, float& b) {
    asm("mov.b64 {%0, %1}, %2;" : "=f"(a), "=f"(b) : "l"(v));
}
__device__ __forceinline__ void ffma2(ull& d, ull a, ull b) {
    asm("fma.rn.f32x2 %0, %1, %2, %0;" : "+l"(d) : "l"(a), "l"(b));
}

// ---------------- persistent scratch (no allocs allowed) ----------------
static __device__ float g_bufA[16777216];   // max: (16,64,128,128)
static __device__ float g_bufB[17040384];   // max: (16,64,129,129)
static __device__ float g_part[8388608];    // split-K partials

static __device__ float g_style0[NB * 256];
static __device__ float g_style1[NB * 128];
static __device__ float g_style2[NB * 128];
static __device__ float g_style3[NB * 64];
static __device__ float g_style4[NB * 64];
static __device__ float g_stylef[NB * 32];

static __device__ float g_demod0[NB * 128];
static __device__ float g_demod1[NB * 128];
static __device__ float g_demod2[NB * 64];
static __device__ float g_demod3[NB * 64];
static __device__ float g_demod4[NB * 32];

__device__ __forceinline__ float* style_ptr(int id) {
    switch (id) {
        case 0: return g_style0;
        case 1: return g_style1;
        case 2: return g_style2;
        case 3: return g_style3;
        case 4: return g_style4;
        default: return g_stylef;
    }
}
__device__ __forceinline__ float* demod_ptr(int id) {
    switch (id) {
        case 0: return g_demod0;
        case 1: return g_demod1;
        case 2: return g_demod2;
        case 3: return g_demod3;
        default: return g_demod4;
    }
}

struct P6 { const float* a[6]; };
struct P5 { const float* a[5]; };

// ---------------- fused style kernel: all 6 layers ----------------
__global__ void style_all_kernel(const float* __restrict__ z, P6 mw, P6 mb) {
    int gw = blockIdx.x * 8 + (threadIdx.x >> 5);
    int lane = threadIdx.x & 31;
    if (gw >= NB * 672) return;
    int b = gw / 672;
    int c = gw - b * 672;
    int L, ci, Ci;
    if (c < 256)      { L = 0; ci = c;       Ci = 256; }
    else if (c < 384) { L = 1; ci = c - 256; Ci = 128; }
    else if (c < 512) { L = 2; ci = c - 384; Ci = 128; }
    else if (c < 576) { L = 3; ci = c - 512; Ci = 64; }
    else if (c < 640) { L = 4; ci = c - 576; Ci = 64; }
    else              { L = 5; ci = c - 640; Ci = 32; }
    const float* zr = z + b * SDIM;
    const float* mr = mw.a[L] + (size_t)ci * SDIM;
    float s = 0.f;
#pragma unroll 4
    for (int k = lane; k < SDIM; k += 32) s += zr[k] * mr[k];
#pragma unroll
    for (int o = 16; o; o >>= 1) s += __shfl_xor_sync(0xffffffffu, s, o);
    if (lane == 0)
        style_ptr(L)[b * Ci + ci] = s * 0.04419417382415922f + mb.a[L][ci];
}

// ---------------- fused demod kernel, wsq inline ----------------
__global__ void demod_all_kernel(P5 w) {
    int gw = blockIdx.x * 8 + (threadIdx.x >> 5);
    int lane = threadIdx.x & 31;
    if (gw >= NB * 416) return;
    int b = gw / 416;
    int c = gw - b * 416;
    int L, co, Co, Ci;
    if (c < 128)      { L = 0; co = c;       Co = 128; Ci = 256; }
    else if (c < 256) { L = 1; co = c - 128; Co = 128; Ci = 128; }
    else if (c < 320) { L = 2; co = c - 256; Co = 64;  Ci = 128; }
    else if (c < 384) { L = 3; co = c - 320; Co = 64;  Ci = 64; }
    else              { L = 4; co = c - 384; Co = 32;  Ci = 64; }
    const float* st = style_ptr(L) + b * Ci;
    const float* wb = w.a[L] + (size_t)co * Ci * 9;
    float s = 0.f;
    for (int ci = lane; ci < Ci; ci += 32) {
        const float* p = wb + ci * 9;
        float wq = 0.f;
#pragma unroll
        for (int t = 0; t < 9; t++) wq += p[t] * p[t];
        float sv = st[ci];
        s += sv * sv * wq;
    }
#pragma unroll
    for (int o = 16; o; o >>= 1) s += __shfl_xor_sync(0xffffffffu, s, o);
    if (lane == 0)
        demod_ptr(L)[b * Co + co] = rsqrtf(s * (1.0f / (float)(Ci * 9)) + 1e-8f);
}

// ---------------- compose (float4): bufA = (fg + (1-mask)*bg) * style0 ------
__global__ void compose_kernel(const float* __restrict__ fg,
                               const float* __restrict__ mask,
                               const float* __restrict__ bg) {
    int idx4 = blockIdx.x * blockDim.x + threadIdx.x;  // over 16*256*256
    int p4 = idx4 & 255;
    int c = (idx4 >> 8) & 255;
    int b = idx4 >> 16;
    float4 m4 = reinterpret_cast<const float4*>(mask)[b * 256 + p4];
    float4 f4 = reinterpret_cast<const float4*>(fg)[idx4];
    float4 g4 = reinterpret_cast<const float4*>(bg)[idx4];
    float s = g_style0[b * 256 + c];
    float4 o;
    o.x = (f4.x + (1.f - m4.x) * g4.x) * s;
    o.y = (f4.y + (1.f - m4.y) * g4.y) * s;
    o.z = (f4.z + (1.f - m4.z) * g4.z) * s;
    o.w = (f4.w + (1.f - m4.w) * g4.w) * s;
    reinterpret_cast<float4*>(g_bufA)[idx4] = o;
}

// ---------------- 3x3 conv, pad 1, f32x2; shift/mask staging; split-K -------
// (exact R12/R16 winner body)
template <int CIN_TOT, int CIN_DO, int COUT, int H, int W, bool SRC_A, int CO_T,
          int NSPLIT>
__global__ __launch_bounds__(256) void conv3x3_kernel(const float* __restrict__ wraw,
                                                      const float* __restrict__ bias,
                                                      int demod_id, int style_id) {
    constexpr int CI_T = 8, TH = 8, TW = 32;
    constexpr int CO_PW = CO_T / 8;
    constexpr int JP = CO_PW / 2;
    constexpr int IN_LD = 36;
    constexpr int W_LD = CO_T + 2;
    constexpr int TILES_X = W / TW;
    __shared__ __align__(16) float s_in[TH + 2][CI_T + 1][IN_LD];
    __shared__ __align__(16) float s_w[CI_T][9][W_LD];

    const float* in = SRC_A ? g_bufA : g_bufB;
    float* out = SRC_A ? g_bufB : g_bufA;
    const float* demod = demod_ptr(demod_id);
    const float* styn = style_ptr(style_id);

    int tid = threadIdx.x;
    int tile = blockIdx.x;
    int tx0 = (tile % TILES_X) * TW;
    int ty0 = (tile / TILES_X) * TH;
    int co_base = blockIdx.y * CO_T;

    int b = blockIdx.z / NSPLIT;
    int half = blockIdx.z % NSPLIT;
    int cin_off = half * CIN_DO;

    int warp = tid >> 5;
    int lane = tid & 31;
    int r = lane >> 2;
    int c0 = (lane & 3) << 3;

    ull acc[JP][8];
#pragma unroll
    for (int jp = 0; jp < JP; jp++)
#pragma unroll
        for (int p = 0; p < 8; p++) acc[jp][p] = 0ull;

    const float wscale = rsqrtf((float)(CIN_TOT * 9));
    const float* in_b = in + (size_t)b * CIN_TOT * H * W;

    int colA = tid & 31;
    int gxA = tx0 + colA - 1;
    bool gxA_ok = (gxA >= 0 && gxA < W);
    int ixB = 32 + (tid & 1);
    int rowB = tid >> 1;
    int iyB = rowB >> 3, ciB = rowB & 7;
    int gxB = tx0 + ixB - 1;
    int gyB = ty0 + iyB - 1;
    bool B_ok = (tid < 160) && gxB >= 0 && gxB < W && gyB >= 0 && gyB < H;

    for (int cb = 0; cb < CIN_DO; cb += CI_T) {
        __syncthreads();
        const float* in_c = in_b + (size_t)(cin_off + cb) * H * W;
#pragma unroll
        for (int k = 0; k < 10; k++) {
            int rowq = (tid + k * 256) >> 5;
            int iy = rowq >> 3;
            int ci = rowq & 7;
            int gy = ty0 + iy - 1;
            float v = 0.f;
            if (gy >= 0 && gy < H && gxA_ok)
                v = in_c[ci * H * W + gy * W + gxA];
            s_in[iy][ci][colA] = v;
        }
        {
            float v = 0.f;
            if (B_ok) v = in_c[ciB * H * W + gyB * W + gxB];
            if (tid < 160) s_in[iyB][ciB][ixB] = v;
        }
#pragma unroll
        for (int k = 0; k < 9; k++) {
            int idx = tid + k * 256;
            int co = idx / (CI_T * 9);
            int rem = idx % (CI_T * 9);
            int ci = rem / 9, tap = rem % 9;
            s_w[ci][tap][co] =
                wraw[((size_t)(co_base + co) * CIN_TOT + cin_off + cb + ci) * 9 +
                     tap] * wscale;
        }
        __syncthreads();
#pragma unroll
        for (int ci = 0; ci < CI_T; ci++) {
#pragma unroll
            for (int ky = 0; ky < 3; ky++) {
                const float4* row4 =
                    reinterpret_cast<const float4*>(&s_in[r + ky][ci][c0]);
                float4 q0 = row4[0];
                float4 q1 = row4[1];
                float4 q2 = row4[2];
                ull xd[10];
                xd[0] = pack2(q0.x, q0.x); xd[1] = pack2(q0.y, q0.y);
                xd[2] = pack2(q0.z, q0.z); xd[3] = pack2(q0.w, q0.w);
                xd[4] = pack2(q1.x, q1.x); xd[5] = pack2(q1.y, q1.y);
                xd[6] = pack2(q1.z, q1.z); xd[7] = pack2(q1.w, q1.w);
                xd[8] = pack2(q2.x, q2.x); xd[9] = pack2(q2.y, q2.y);
#pragma unroll
                for (int kx = 0; kx < 3; kx++) {
#pragma unroll
                    for (int jp = 0; jp < JP; jp++) {
                        ull w2 = *reinterpret_cast<const ull*>(
                            &s_w[ci][ky * 3 + kx][warp * CO_PW + jp * 2]);
#pragma unroll
                        for (int p = 0; p < 8; p++) ffma2(acc[jp][p], w2, xd[kx + p]);
                    }
                }
            }
        }
    }
    int oy = ty0 + r;
#pragma unroll
    for (int jp = 0; jp < JP; jp++) {
        float vlo[8], vhi[8];
#pragma unroll
        for (int p = 0; p < 8; p++) unpack2(acc[jp][p], vlo[p], vhi[p]);
#pragma unroll
        for (int h = 0; h < 2; h++) {
            int co = co_base + warp * CO_PW + jp * 2 + h;
            const float* src = h ? vhi : vlo;
            if (NSPLIT > 1) {
                float* pp = g_part +
                            (((size_t)half * NB + b) * COUT + co) * H * W +
                            oy * W + tx0 + c0;
                float4 o0, o1;
                o0.x = src[0]; o0.y = src[1]; o0.z = src[2]; o0.w = src[3];
                o1.x = src[4]; o1.y = src[5]; o1.z = src[6]; o1.w = src[7];
                reinterpret_cast<float4*>(pp)[0] = o0;
                reinterpret_cast<float4*>(pp)[1] = o1;
            } else {
                float dm = demod[b * COUT + co];
                float bi = bias[co];
                float sn = styn[b * COUT + co];
                float* op = out + (size_t)b * COUT * H * W +
                            (size_t)co * H * W + oy * W + tx0 + c0;
                float4 o0, o1;
                float vv[8];
#pragma unroll
                for (int p = 0; p < 8; p++) {
                    float v = src[p] * dm + bi;
                    vv[p] = (v > 0.f ? v : 0.2f * v) * 1.41421356237309515f * sn;
                }
                o0.x = vv[0]; o0.y = vv[1]; o0.z = vv[2]; o0.w = vv[3];
                o1.x = vv[4]; o1.y = vv[5]; o1.z = vv[6]; o1.w = vv[7];
                reinterpret_cast<float4*>(op)[0] = o0;
                reinterpret_cast<float4*>(op)[1] = o1;
            }
        }
    }
}

// ---------------- split-K combine (float4) ----------------
template <int CO, int HW, int NHALF, bool DST_B>
__global__ void combine_kernel(const float* __restrict__ bias,
                               int demod_id, int style_id) {
    int idx4 = blockIdx.x * blockDim.x + threadIdx.x;   // over NB*CO*HW/4
    constexpr int COHW4 = CO * HW / 4;
    constexpr int HW4 = HW / 4;
    int b = idx4 / COHW4;
    int co = (idx4 / HW4) & (CO - 1);
    const float4* gp = reinterpret_cast<const float4*>(g_part);
    float4 p = gp[idx4];
#pragma unroll
    for (int h = 1; h < NHALF; h++) {
        float4 q = gp[idx4 + (size_t)h * NB * COHW4];
        p.x += q.x; p.y += q.y; p.z += q.z; p.w += q.w;
    }
    float dm = demod_ptr(demod_id)[b * CO + co];
    float bi = bias[co];
    float sn = style_ptr(style_id)[b * CO + co] * 1.41421356237309515f;
    float4 o;
    float v;
    v = p.x * dm + bi; o.x = (v > 0.f ? v : 0.2f * v) * sn;
    v = p.y * dm + bi; o.y = (v > 0.f ? v : 0.2f * v) * sn;
    v = p.z * dm + bi; o.z = (v > 0.f ? v : 0.2f * v) * sn;
    v = p.w * dm + bi; o.w = (v > 0.f ? v : 0.2f * v) * sn;
    reinterpret_cast<float4*>(DST_B ? g_bufB : g_bufA)[idx4] = o;
}

// ---------------- transposed conv: dense interior, CI_T=16 ------------------
// Same body as R12 winner; CI_T raised to 16 (halves barrier/stage count).
template <int CIN, int COUT, int HIN, bool SRC_A>
__global__ __launch_bounds__(256) void tconv_kernel(const float* __restrict__ wraw,
                                                    int demod_id) {
    constexpr int HOUT = 2 * HIN + 1;
    constexpr int CO_T = 32, CI_T = 16, TH = 8, TW = 32;
    constexpr int IR = 6, ICW = 18, IC_LD = 19;
    constexpr int W_LD = 34;
    constexpr int TILES_X = (2 * HIN) / TW;
    __shared__ __align__(16) float s_in[CI_T][IR][IC_LD];
    __shared__ __align__(16) float s_w[CI_T][9][W_LD];

    const float* in = SRC_A ? g_bufA : g_bufB;
    float* out = SRC_A ? g_bufB : g_bufA;
    const float* demod = demod_ptr(demod_id);

    int tid = threadIdx.x;
    int tile = blockIdx.x;
    int tx0 = (tile % TILES_X) * TW;
    int ty0 = (tile / TILES_X) * TH;
    int co_base = blockIdx.y * CO_T;
    int b = blockIdx.z;

    int co_grp = tid >> 6;
    int lane = tid & 31;
    int wrp = tid >> 5;
    int r = 2 * ((lane >> 3) & 3) + (wrp & 1);
    int c0 = (lane & 7) << 2;
    int h = c0 >> 1;

    int iy_base = (ty0 >> 1) - 1;
    int jx_base = (tx0 >> 1) - 1;

    ull acc[4][4];
#pragma unroll
    for (int jp = 0; jp < 4; jp++)
#pragma unroll
        for (int p = 0; p < 4; p++) acc[jp][p] = 0ull;

    const float wscale = rsqrtf((float)(CIN * 9));
    const float* in_b = in + (size_t)b * CIN * HIN * HIN;

    for (int cb = 0; cb < CIN; cb += CI_T) {
        __syncthreads();
        for (int idx = tid; idx < CI_T * IR * ICW; idx += 256) {
            int ci = idx / (IR * ICW);
            int rem = idx % (IR * ICW);
            int iy = rem / ICW, ix = rem % ICW;
            int gy = iy_base + iy, gx = jx_base + ix;
            float v = 0.f;
            if (gy >= 0 && gy < HIN && gx >= 0 && gx < HIN)
                v = in_b[(size_t)(cb + ci) * HIN * HIN + gy * HIN + gx];
            s_in[ci][iy][ix] = v;
        }
        for (int idx = tid; idx < CO_T * CI_T * 9; idx += 256) {
            int co = idx / (CI_T * 9);
            int rem = idx % (CI_T * 9);
            int ci = rem / 9, tap = rem % 9;
            s_w[ci][tap][co] =
                wraw[((size_t)(co_base + co) * CIN + cb + ci) * 9 + tap] * wscale;
        }
        __syncthreads();
#pragma unroll
        for (int ci = 0; ci < CI_T; ci++) {
            int ky0 = r & 1;
            for (int ky = ky0; ky < 3; ky += 2) {
                int ir = ((r + ky - 2) >> 1) + 1;
                float x0v = s_in[ci][ir][h];
                float x1v = s_in[ci][ir][h + 1];
                float x2v = s_in[ci][ir][h + 2];
                ull xd0 = pack2(x0v, x0v);
                ull xd1 = pack2(x1v, x1v);
                ull xd2 = pack2(x2v, x2v);
                int wr = (2 - ky) * 3;
#pragma unroll
                for (int jp = 0; jp < 4; jp++) {
                    int co = co_grp * 8 + jp * 2;
                    ull w0 = *reinterpret_cast<const ull*>(&s_w[ci][wr + 0][co]);
                    ull w1 = *reinterpret_cast<const ull*>(&s_w[ci][wr + 1][co]);
                    ull w2 = *reinterpret_cast<const ull*>(&s_w[ci][wr + 2][co]);
                    ffma2(acc[jp][0], w2, xd0);
                    ffma2(acc[jp][0], w0, xd1);
                    ffma2(acc[jp][1], w1, xd1);
                    ffma2(acc[jp][2], w2, xd1);
                    ffma2(acc[jp][2], w0, xd2);
                    ffma2(acc[jp][3], w1, xd2);
                }
            }
        }
    }
    int oy = ty0 + r;
    float* out_b = out + (size_t)b * COUT * HOUT * HOUT;
#pragma unroll
    for (int jp = 0; jp < 4; jp++) {
#pragma unroll
        for (int hh = 0; hh < 2; hh++) {
            int co = co_base + co_grp * 8 + jp * 2 + hh;
            float dm = demod[b * COUT + co];
#pragma unroll
            for (int p = 0; p < 4; p++) {
                float lo, hi;
                unpack2(acc[jp][p], lo, hi);
                out_b[(size_t)co * HOUT * HOUT + oy * HOUT + tx0 + c0 + p] =
                    (hh ? hi : lo) * dm;
            }
        }
    }
}

// ---------------- tconv edge strips (unchanged) ------------------
template <int CIN, int COUT, int HIN, bool SRC_A>
__global__ __launch_bounds__(256) void tconv_edge_kernel(
    const float* __restrict__ wraw, int demod_id) {
    constexpr int HOUT = 2 * HIN + 1;
    __shared__ float s_line[CIN][HIN];
    __shared__ float s_w3[CIN][3][33];

    const float* in = SRC_A ? g_bufA : g_bufB;
    float* out = SRC_A ? g_bufB : g_bufA;

    int s = blockIdx.y;
    int co_base = blockIdx.x * 32;
    int b = blockIdx.z;
    int tid = threadIdx.x;
    const float* in_b = in + (size_t)b * CIN * HIN * HIN;

    for (int e = tid; e < CIN * HIN; e += 256) {
        int ci = e / HIN, t = e % HIN;
        s_line[ci][t] = (s == 0)
            ? in_b[(size_t)ci * HIN * HIN + t * HIN + (HIN - 1)]
            : in_b[(size_t)ci * HIN * HIN + (HIN - 1) * HIN + t];
    }
    const float wscale = rsqrtf((float)(CIN * 9));
    for (int e = tid; e < 32 * CIN * 3; e += 256) {
        int co = e / (CIN * 3);
        int rem = e % (CIN * 3);
        int ci = rem / 3, k = rem % 3;
        int widx = (s == 0) ? ((2 - k) * 3 + 2) : (2 * 3 + (2 - k));
        s_w3[ci][k][co] =
            wraw[((size_t)(co_base + co) * CIN + ci) * 9 + widx] * wscale;
    }
    __syncthreads();

    int co = tid & 31;
    float dm = demod_ptr(demod_id)[b * COUT + co_base + co];
    float* out_b = out + ((size_t)b * COUT + co_base + co) * HOUT * HOUT;
    int nmax = HOUT - s;
    for (int n = tid >> 5; n < nmax; n += 8) {
        float acc = 0.f;
        if (n & 1) {
            int iy = (n - 1) >> 1;
#pragma unroll 4
            for (int ci = 0; ci < CIN; ci++)
                acc += s_line[ci][iy] * s_w3[ci][1][co];
        } else {
            int hh = n >> 1;
            if (hh >= 1) {
#pragma unroll 4
                for (int ci = 0; ci < CIN; ci++)
                    acc += s_line[ci][hh - 1] * s_w3[ci][0][co];
            }
            if (hh < HIN) {
#pragma unroll 4
                for (int ci = 0; ci < CIN; ci++)
                    acc += s_line[ci][hh] * s_w3[ci][2][co];
            }
        }
        acc *= dm;
        if (s == 0) out_b[n * HOUT + (HOUT - 1)] = acc;
        else out_b[(HOUT - 1) * HOUT + n] = acc;
    }
}

// ---------------- 4x4 blur + bias + leaky*sqrt2*style_next ----------------
template <int C, int HIN, bool SRC_A>
__global__ __launch_bounds__(256) void blur_kernel(const float* __restrict__ bias,
                                                   int style_id) {
    constexpr int HOUT = HIN - 1;
    constexpr int TH = 16, TW = 32;
    constexpr int TILES_X = HOUT / TW;
    __shared__ float s[TH + 3][TW + 4];

    const float* in = SRC_A ? g_bufA : g_bufB;
    float* out = SRC_A ? g_bufB : g_bufA;

    int tile = blockIdx.x;
    int x0 = (tile % TILES_X) * TW;
    int y0 = (tile / TILES_X) * TH;
    int c = blockIdx.y, b = blockIdx.z;
    const float* ip = in + ((size_t)b * C + c) * HIN * HIN;

    for (int idx = threadIdx.x; idx < (TH + 3) * (TW + 3); idx += 256) {
        int iy = idx / (TW + 3), ix = idx % (TW + 3);
        int gy = y0 + iy - 1, gx = x0 + ix - 1;
        float v = 0.f;
        if (gy >= 0 && gy < HIN && gx >= 0 && gx < HIN) v = ip[gy * HIN + gx];
        s[iy][ix] = v;
    }
    __syncthreads();

    const float c4[4] = {0.25f, 0.75f, 0.75f, 0.25f};
    float bi = bias[c];
    float sn = style_ptr(style_id)[b * C + c];
    float* op = out + ((size_t)b * C + c) * HOUT * HOUT;
#pragma unroll
    for (int q = 0; q < 2; q++) {
        int px = threadIdx.x + q * 256;
        int ly = px >> 5, lx = px & 31;
        float a = 0.f;
#pragma unroll
        for (int ky = 0; ky < 4; ky++) {
            float rs = 0.f;
#pragma unroll
            for (int kx = 0; kx < 4; kx++) rs += c4[kx] * s[ly + ky][lx + kx];
            a += c4[ky] * rs;
        }
        a += bi;
        a = (a > 0.f ? a : 0.2f * a) * 1.41421356237309515f * sn;
        op[(y0 + ly) * HOUT + x0 + lx] = a;
    }
}

// ---------------- final 1x1 (float4): 32 -> 3 of 4 ch, + out_bias -----------
__global__ void final_kernel(const float* __restrict__ finw,
                             const float* __restrict__ outb,
                             float* __restrict__ out) {
    int idx4 = blockIdx.x * blockDim.x + threadIdx.x;  // over 16*4096
    int b = idx4 >> 12;
    int p4 = idx4 & 4095;
    const float4* ib = reinterpret_cast<const float4*>(g_bufB) +
                       (size_t)b * 32 * 4096 + p4;
    float4 a0 = {0.f, 0.f, 0.f, 0.f};
    float4 a1 = {0.f, 0.f, 0.f, 0.f};
    float4 a2 = {0.f, 0.f, 0.f, 0.f};
#pragma unroll
    for (int ci = 0; ci < 32; ci++) {
        float4 v = ib[(size_t)ci * 4096];
        float w0 = finw[ci], w1 = finw[32 + ci], w2 = finw[64 + ci];
        a0.x = fmaf(w0, v.x, a0.x); a0.y = fmaf(w0, v.y, a0.y);
        a0.z = fmaf(w0, v.z, a0.z); a0.w = fmaf(w0, v.w, a0.w);
        a1.x = fmaf(w1, v.x, a1.x); a1.y = fmaf(w1, v.y, a1.y);
        a1.z = fmaf(w1, v.z, a1.z); a1.w = fmaf(w1, v.w, a1.w);
        a2.x = fmaf(w2, v.x, a2.x); a2.y = fmaf(w2, v.y, a2.y);
        a2.z = fmaf(w2, v.z, a2.z); a2.w = fmaf(w2, v.w, a2.w);
    }
    const float sc = rsqrtf(32.0f);
    float4* o4 = reinterpret_cast<float4*>(out) + (size_t)b * 3 * 4096;
    float4 o;
    o.x = a0.x * sc + outb[0]; o.y = a0.y * sc + outb[0];
    o.z = a0.z * sc + outb[0]; o.w = a0.w * sc + outb[0];
    o4[p4] = o;
    o.x = a1.x * sc + outb[1]; o.y = a1.y * sc + outb[1];
    o.z = a1.z * sc + outb[1]; o.w = a1.w * sc + outb[1];
    o4[4096 + p4] = o;
    o.x = a2.x * sc + outb[2]; o.y = a2.y * sc + outb[2];
    o.z = a2.z * sc + outb[2]; o.w = a2.w * sc + outb[2];
    o4[2 * 4096 + p4] = o;
}

// ------------------------------------------------------------------------
extern "C" void kernel_launch(void* const* d_in, const int* in_sizes, int n_in,
                              void* d_out, int out_size) {
    (void)in_sizes; (void)n_in; (void)out_size;
    const float* fg = (const float*)d_in[0];
    const float* mask = (const float*)d_in[1];
    const float* bg = (const float*)d_in[2];
    const float* z = (const float*)d_in[3];
    const float* l_w[5]  = {(const float*)d_in[4],  (const float*)d_in[8],
                            (const float*)d_in[12], (const float*)d_in[16],
                            (const float*)d_in[20]};
    const float* l_mw[5] = {(const float*)d_in[5],  (const float*)d_in[9],
                            (const float*)d_in[13], (const float*)d_in[17],
                            (const float*)d_in[21]};
    const float* l_mb[5] = {(const float*)d_in[6],  (const float*)d_in[10],
                            (const float*)d_in[14], (const float*)d_in[18],
                            (const float*)d_in[22]};
    const float* l_b[5]  = {(const float*)d_in[7],  (const float*)d_in[11],
                            (const float*)d_in[15], (const float*)d_in[19],
                            (const float*)d_in[23]};
    const float* finw = (const float*)d_in[24];
    const float* fin_mw = (const float*)d_in[25];
    const float* fin_mb = (const float*)d_in[26];
    const float* outb = (const float*)d_in[27];

    // fused setup: 2 kernels
    P6 mw6, mb6;
    for (int l = 0; l < 5; l++) { mw6.a[l] = l_mw[l]; mb6.a[l] = l_mb[l]; }
    mw6.a[5] = fin_mw; mb6.a[5] = fin_mb;
    style_all_kernel<<<1344, 256>>>(z, mw6, mb6);
    P5 w5;
    for (int l = 0; l < 5; l++) w5.a[l] = l_w[l];
    demod_all_kernel<<<832, 256>>>(w5);

    // compose + modulate for layer 0 -> bufA (float4)
    compose_kernel<<<(NB * 256 * 256) / 256, 256>>>(fg, mask, bg);

    // l0: 256->128 @32x32, split-K=4 -> 1024 CTAs
    conv3x3_kernel<256, 64, 128, 32, 32, true, 32, 4>
        <<<dim3(4, 4, 64), 256>>>(l_w[0], l_b[0], 0, 1);
    combine_kernel<128, 1024, 4, true><<<2048, 256>>>(l_b[0], 0, 1);
    // l1: tconv 128->128, 32 -> 65 (B -> A): dense 64x64 interior + edges
    tconv_kernel<128, 128, 32, false><<<dim3(16, 4, NB), 256>>>(l_w[1], 1);
    tconv_edge_kernel<128, 128, 32, false><<<dim3(4, 2, NB), 256>>>(l_w[1], 1);
    // blur 65 -> 64 + act + style2   (A -> B)
    blur_kernel<128, 65, true><<<dim3(8, 128, NB), 256>>>(l_b[1], 2);
    // l2: 128->64 @64x64, split-K=2 -> 1024 CTAs
    conv3x3_kernel<128, 64, 64, 64, 64, false, 32, 2>
        <<<dim3(16, 2, 32), 256>>>(l_w[2], l_b[2], 2, 3);
    combine_kernel<64, 4096, 2, false><<<4096, 256>>>(l_b[2], 2, 3);
    // l3: tconv 64->64, 64 -> 129 (A -> B): dense 128x128 interior + edges
    tconv_kernel<64, 64, 64, true><<<dim3(64, 2, NB), 256>>>(l_w[3], 3);
    tconv_edge_kernel<64, 64, 64, true><<<dim3(2, 2, NB), 256>>>(l_w[3], 3);
    // blur 129 -> 128 + act + style4   (B -> A)
    blur_kernel<64, 129, false><<<dim3(32, 64, NB), 256>>>(l_b[3], 4);
    // l4: 64->32 @128x128   (A -> B)
    conv3x3_kernel<64, 64, 32, 128, 128, true, 32, 1>
        <<<dim3(64, 1, 16), 256>>>(l_w[4], l_b[4], 4, 5);
    // final 1x1 32->3 + out_bias   (B -> d_out, float4)
    final_kernel<<<(NB * 4096) / 256, 256>>>(finw, outb, (float*)d_out);
}